// round 13
// baseline (speedup 1.0000x reference)
#include <cuda_runtime.h>
#include <cuda_fp16.h>
#include <math.h>
#include <stdint.h>

#define Hdim 512
#define SHdim 120
#define Bdim 1024
#define Sdim 64
#define H3 1536
#define H4 2048
#define Mrows (Bdim*Sdim)
#define LD 80          // 32-half (64B) rows + 16B pad
#define LD64 144       // 64-half (128B) rows + 16B pad
#define WLD 1040       // resident Whh rows: 512 halves (1024B) + 16B pad

// ----------------------------- device scratch ------------------------------
__device__ float g_G[Sdim*Bdim];
__device__ __half g_xg16[(size_t)Sdim*Bdim*H3];      // xg in fp16
__device__ __half g_h16[2][Bdim*Hdim];               // fp16 MMA operand image
__device__ __half g_C16[(size_t)Mrows*Hdim];         // C fp16
__device__ __half g_Wih16[H3*Hdim];
__device__ __half g_Whh16[H3*Hdim];
__device__ __half g_fc1w16[128*H4];
__device__ unsigned g_flag[16*8*32];                 // [bt][by] steps done, 128B stride

// fast transcendentals: rel err ~1e-6 — far below fp16 noise
__device__ __forceinline__ float sigmoidf_(float x){
    return __fdividef(1.0f, 1.0f + __expf(-x));
}
__device__ __forceinline__ float tanhf_(float x){
    return __fdividef(2.0f, 1.0f + __expf(-2.0f * x)) - 1.0f;
}

// ----------------------------- asm helpers ---------------------------------
__device__ __forceinline__ uint32_t smem_u32(const void* p){
    uint32_t a;
    asm("{ .reg .u64 t; cvta.to.shared.u64 t, %1; cvt.u32.u64 %0, t; }" : "=r"(a) : "l"(p));
    return a;
}
__device__ __forceinline__ void mma16816(float* c, uint32_t a0, uint32_t a1,
                                         uint32_t a2, uint32_t a3,
                                         uint32_t b0, uint32_t b1){
    asm volatile(
        "mma.sync.aligned.m16n8k16.row.col.f32.f16.f16.f32 "
        "{%0,%1,%2,%3},{%4,%5,%6,%7},{%8,%9},{%0,%1,%2,%3};"
        : "+f"(c[0]), "+f"(c[1]), "+f"(c[2]), "+f"(c[3])
        : "r"(a0), "r"(a1), "r"(a2), "r"(a3), "r"(b0), "r"(b1));
}
#define LDSM4(r0,r1,r2,r3, addr) \
    asm volatile("ldmatrix.sync.aligned.m8n8.x4.shared.b16 {%0,%1,%2,%3}, [%4];" \
        : "=r"(r0), "=r"(r1), "=r"(r2), "=r"(r3) : "r"(addr))
#define STS16(dst, v) asm volatile("st.shared.v4.b32 [%0],{%1,%2,%3,%4};" \
        :: "r"(dst), "r"((v).x), "r"((v).y), "r"((v).z), "r"((v).w))
#define CP16(dst, src) asm volatile("cp.async.cg.shared.global [%0], [%1], 16;" \
        :: "r"(dst), "l"(src))
#define CP_COMMIT() asm volatile("cp.async.commit_group;" ::: "memory")
#define CP_WAIT0()  asm volatile("cp.async.wait_group 0;" ::: "memory")
#define CP_WAIT1()  asm volatile("cp.async.wait_group 1;" ::: "memory")
#define CP_WAIT2()  asm volatile("cp.async.wait_group 2;" ::: "memory")

__device__ __forceinline__ void wait_flag(const unsigned* f, unsigned s){
    if (s == 0) return;
    unsigned v;
    do {
        asm volatile("ld.acquire.gpu.u32 %0, [%1];" : "=r"(v) : "l"(f));
    } while (v < s);
}

// ----------------------------- init / convert ------------------------------
__global__ void zero_init_kernel(){
    int i = blockIdx.x * blockDim.x + threadIdx.x;
    if (i < Bdim * Hdim) g_h16[0][i] = __float2half_rn(0.0f);
    if (i < 16*8*32) g_flag[i] = 0u;
}
__device__ __forceinline__ uint2 cvt4h(float4 v){
    __half2 h0(__float2half_rn(v.x), __float2half_rn(v.y));
    __half2 h1(__float2half_rn(v.z), __float2half_rn(v.w));
    uint2 o; o.x = *(uint32_t*)&h0; o.y = *(uint32_t*)&h1; return o;
}
__global__ void cvt_C16_kernel(const float* __restrict__ src){
    size_t i = (size_t)blockIdx.x * blockDim.x + threadIdx.x;   // 8388608 float4
    ((uint2*)g_C16)[i] = cvt4h(((const float4*)src)[i]);
}
__global__ void cvt_W16_kernel(const float* __restrict__ wih,
                               const float* __restrict__ whh,
                               const float* __restrict__ fc1w){
    int i = blockIdx.x * blockDim.x + threadIdx.x;
    const int nW = H3 * Hdim / 4;                    // 196608
    const int nF = SHdim * H4 / 4;                   // 61440
    if (i < nW) {
        ((uint2*)g_Wih16)[i] = cvt4h(((const float4*)wih)[i]);
    } else if (i < 2*nW) {
        int j = i - nW;
        ((uint2*)g_Whh16)[j] = cvt4h(((const float4*)whh)[j]);
    } else if (i < 2*nW + nF) {
        int j = i - 2*nW;
        ((uint2*)g_fc1w16)[j] = cvt4h(((const float4*)fc1w)[j]);
    } else {
        int j = i - 2*nW - nF;                       // 4096 pad uint2
        ((uint2*)g_fc1w16)[nF + j] = make_uint2(0u, 0u);
    }
}

// ---------------------------------------------------------------------------
// Gate network: one C16 read per chunk feeds all 4 feat parts.
// CTA m128 x n128 (120 real), 512 threads; warps 4m x 4n; 16 chunks k32.
// ---------------------------------------------------------------------------
#define GAp (128*LD)               // 10240 per part image
#define GA4 (4*GAp)                // 40960 A block (4 parts)
#define GST3 (GA4 + 4*GAp)         // stage = A(4) + B(4) = 81920

__global__ __launch_bounds__(512, 1) void G_mma(
    const float* __restrict__ Q, const float* __restrict__ PM,
    const float* __restrict__ fc1b, const float* __restrict__ fc2w,
    const float* __restrict__ fc2b)
{
    extern __shared__ __align__(16) char smg2[];
    __shared__ __align__(16) float sQP[2][2][Hdim];   // [q/pm][b_local][k]
    __shared__ __align__(16) float red[4][128];       // fc2 cross-warp partials
    const uint32_t sb = smem_u32(smg2);
    const int tid = threadIdx.x, lane = tid & 31, wid = tid >> 5;
    const int wm = wid >> 2, wn = wid & 3;            // 4m x 4n, warp m32 x n32
    const int m0 = blockIdx.x * 128;

    {
        const int b_base = m0 >> 6;
        for (int q = tid; q < 2 * Hdim / 4; q += 512) {
            const int bl = q / (Hdim/4), u = q % (Hdim/4);
            *(float4*)&sQP[0][bl][u*4] = *(const float4*)(Q  + (size_t)(b_base+bl)*Hdim + u*4);
            *(float4*)&sQP[1][bl][u*4] = *(const float4*)(PM + (size_t)(b_base+bl)*Hdim + u*4);
        }
    }
    __syncthreads();

    float acc[2][4][4];                               // [mf][nb][frag]
    #pragma unroll
    for (int mf = 0; mf < 2; mf++)
        #pragma unroll
        for (int nb = 0; nb < 4; nb++)
            #pragma unroll
            for (int d = 0; d < 4; d++) acc[mf][nb][d] = 0.0f;

    auto G_fetchC = [&](int c, uint4* rr) {
        const int base0 = c * 32;                     // 512 u4, one per thread
        const int r = tid >> 2, u = tid & 3;
        rr[0] = *(const uint4*)(g_C16 + (size_t)(m0 + r) * Hdim + base0 + u * 8);
    };
    auto G_storeA = [&](int c, uint32_t buf, const uint4* rr) {
        const int base0 = c * 32;
        const int r = tid >> 2, u = tid & 3;
        const __half* ch = (const __half*)&rr[0];
        float cf[8];
        #pragma unroll
        for (int j = 0; j < 8; j++) cf[j] = __half2float(ch[j]);
        const float* qv = &sQP[0][r >> 6][base0 + u * 8];
        const float* pv = &sQP[1][r >> 6][base0 + u * 8];
        #pragma unroll
        for (int part = 0; part < 4; part++) {
            const float* vv = (part & 1) ? pv : qv;
            uint32_t o[4];
            #pragma unroll
            for (int j = 0; j < 4; j++) {
                const float x0 = (part < 2) ? cf[2*j]   * vv[2*j]
                                            : fabsf(cf[2*j]   - vv[2*j]);
                const float x1 = (part < 2) ? cf[2*j+1] * vv[2*j+1]
                                            : fabsf(cf[2*j+1] - vv[2*j+1]);
                const __half2 hh = __floats2half2_rn(x0, x1);
                o[j] = *(const uint32_t*)&hh;
            }
            const uint4 v4 = make_uint4(o[0], o[1], o[2], o[3]);
            STS16(buf + part * GAp + r * LD + u * 16, v4);
        }
    };
    auto G_cpB = [&](int c, uint32_t buf) {
        const int base0 = c * 32;
        #pragma unroll
        for (int i = 0; i < 4; i++) {               // 2048 u4 (4 parts x 512)
            const int q = tid + i * 512;
            const int part = q >> 9, rem = q & 511;
            const int r = rem >> 2, u = rem & 3;
            CP16(buf + GA4 + part * GAp + r * LD + u * 16,
                 g_fc1w16 + (size_t)r * H4 + part * 512 + base0 + u * 8);
        }
    };

    uint4 rr[1];
    G_fetchC(0, rr);
    G_cpB(0, sb);
    CP_COMMIT();
    G_storeA(0, sb, rr);
    CP_WAIT0();
    __syncthreads();

    const uint32_t a_lane = (lane & 15) * LD + (lane >> 4) * 16;
    const uint32_t b_lane = ((lane >> 4) * 8 + (lane & 7)) * LD + ((lane >> 3) & 1) * 16;

    for (int c = 0; c < 16; c++) {
        const uint32_t cur = sb + (c & 1) * GST3;
        const uint32_t nxt = sb + ((c + 1) & 1) * GST3;
        if (c < 15) {
            G_fetchC(c + 1, rr);
            G_cpB(c + 1, nxt);
        }
        CP_COMMIT();
        #pragma unroll
        for (int part = 0; part < 4; part++) {
            #pragma unroll
            for (int kk = 0; kk < 2; kk++) {
                uint32_t a[2][4];
                #pragma unroll
                for (int mf = 0; mf < 2; mf++)
                    LDSM4(a[mf][0], a[mf][1], a[mf][2], a[mf][3],
                          cur + part * GAp + (wm * 32 + mf * 16) * LD + kk * 32 + a_lane);
                #pragma unroll
                for (int nbp = 0; nbp < 2; nbp++) {
                    uint32_t b0, b1, b2, b3;
                    LDSM4(b0, b1, b2, b3,
                          cur + GA4 + part * GAp + (wn * 32 + nbp * 16) * LD + kk * 32 + b_lane);
                    #pragma unroll
                    for (int mf = 0; mf < 2; mf++) {
                        mma16816(acc[mf][nbp*2],   a[mf][0], a[mf][1], a[mf][2], a[mf][3], b0, b1);
                        mma16816(acc[mf][nbp*2+1], a[mf][0], a[mf][1], a[mf][2], a[mf][3], b2, b3);
                    }
                }
            }
        }
        if (c < 15) G_storeA(c + 1, nxt, rr);
        CP_WAIT0();
        __syncthreads();
    }

    // fc2 epilogue: warp-local tanh+dot over warp's n32, then 4-way wn reduce
    #pragma unroll
    for (int mf = 0; mf < 2; mf++) {
        #pragma unroll
        for (int half = 0; half < 2; half++) {
            float partial = 0.0f;
            #pragma unroll
            for (int nb = 0; nb < 4; nb++) {
                #pragma unroll
                for (int cc = 0; cc < 2; cc++) {
                    const int n = wn * 32 + nb * 8 + (lane & 3) * 2 + cc;
                    if (n < SHdim)
                        partial += fc2w[n] * tanhf_(acc[mf][nb][half*2+cc] + fc1b[n]);
                }
            }
            partial += __shfl_xor_sync(0xffffffffu, partial, 1);
            partial += __shfl_xor_sync(0xffffffffu, partial, 2);
            if ((lane & 3) == 0)
                red[wn][wm * 32 + mf * 16 + half * 8 + (lane >> 2)] = partial;
        }
    }
    __syncthreads();
    if (tid < 128) {
        const int m = m0 + tid;
        g_G[(m & 63) * Bdim + (m >> 6)] =
            sigmoidf_(red[0][tid] + red[1][tid] + red[2][tid] + red[3][tid] + fc2b[0]);
    }
}

// ---------------------------------------------------------------------------
// xg = C @ Wih^T + b (fp16, single term). CTA 128m x 256n, 512 threads,
// cp.async 4-stage, 8 chunks of k64. Output fp16.
// ---------------------------------------------------------------------------
#define XA2 (128*LD64)             // 18432
#define XST (XA2 + 256*LD64)       // 55296

__device__ __forceinline__ void xg_ld(uint32_t buf, int tid, int m0, int n0, int c){
    const int k0 = c * 64;
    #pragma unroll
    for (int i = 0; i < 2; i++) {            // A: 1024 u4
        const int q = tid + i * 512;
        const int r = q >> 3, u = q & 7;
        CP16(buf + r * LD64 + u * 16, g_C16 + (size_t)(m0 + r) * Hdim + k0 + u * 8);
    }
    #pragma unroll
    for (int i = 0; i < 4; i++) {            // B: 2048 u4
        const int q = tid + i * 512;
        const int r = q >> 3, u = q & 7;
        CP16(buf + XA2 + r * LD64 + u * 16, g_Wih16 + (size_t)(n0 + r) * Hdim + k0 + u * 8);
    }
}

__global__ __launch_bounds__(512, 1) void xg_mma(const float* __restrict__ bih)
{
    extern __shared__ __align__(16) char smx[];
    const uint32_t sb = smem_u32(smx);
    const int tid = threadIdx.x, lane = tid & 31, wid = tid >> 5;
    const int wm = wid >> 3, wn = wid & 7;
    const int m0 = blockIdx.x * 128, n0 = blockIdx.y * 256;

    float acc[4][4][4];
    #pragma unroll
    for (int a = 0; a < 4; a++)
        #pragma unroll
        for (int b = 0; b < 4; b++)
            #pragma unroll
            for (int d = 0; d < 4; d++) acc[a][b][d] = 0.0f;

    xg_ld(sb, tid, m0, n0, 0); CP_COMMIT();
    xg_ld(sb + XST, tid, m0, n0, 1); CP_COMMIT();
    xg_ld(sb + 2*XST, tid, m0, n0, 2); CP_COMMIT();

    const uint32_t a_lrow = (lane & 15) * LD64 + (lane >> 4) * 16;
    const uint32_t b_lrow = ((lane >> 4) * 8 + (lane & 7)) * LD64 + ((lane >> 3) & 1) * 16;

    for (int c = 0; c < 8; c++) {
        CP_WAIT2();
        __syncthreads();
        if (c + 3 < 8) xg_ld(sb + ((c + 3) & 3) * XST, tid, m0, n0, c + 3);
        CP_COMMIT();
        const uint32_t cur = sb + (c & 3) * XST;
        #pragma unroll
        for (int kk = 0; kk < 4; kk++) {
            uint32_t a[4][4];
            #pragma unroll
            for (int mf = 0; mf < 4; mf++)
                LDSM4(a[mf][0], a[mf][1], a[mf][2], a[mf][3],
                      cur + (wm * 64 + mf * 16) * LD64 + kk * 32 + a_lrow);
            #pragma unroll
            for (int nfp = 0; nfp < 2; nfp++) {
                uint32_t b0, b1, b2, b3;
                LDSM4(b0, b1, b2, b3,
                      cur + XA2 + (wn * 32 + nfp * 16) * LD64 + kk * 32 + b_lrow);
                #pragma unroll
                for (int mf = 0; mf < 4; mf++) {
                    mma16816(acc[mf][nfp*2],   a[mf][0], a[mf][1], a[mf][2], a[mf][3], b0, b1);
                    mma16816(acc[mf][nfp*2+1], a[mf][0], a[mf][1], a[mf][2], a[mf][3], b2, b3);
                }
            }
        }
    }

    #pragma unroll
    for (int mf = 0; mf < 4; mf++) {
        #pragma unroll
        for (int half = 0; half < 2; half++) {
            const int m = m0 + wm * 64 + mf * 16 + (lane >> 2) + half * 8;
            const size_t ob = ((size_t)(m & 63) * Bdim + (m >> 6)) * H3;
            #pragma unroll
            for (int nf = 0; nf < 4; nf++) {
                const int jj = n0 + wn * 32 + nf * 8 + (lane & 3) * 2;
                const float ox = acc[mf][nf][half*2+0] + bih[jj];
                const float oy = acc[mf][nf][half*2+1] + bih[jj+1];
                *(__half2*)(g_xg16 + ob + jj) = __floats2half2_rn(ox, oy);
            }
        }
    }
}

// ---------------------------------------------------------------------------
// Persistent GRU: Whh resident; register-carried h; dataflow flags with
// SINGLE-THREAD polls folded into the existing per-chunk __syncthreads.
// Chunk c of step s reads only CTA (bt, by=c)'s h slice -> gate on its flag.
// ---------------------------------------------------------------------------
#define WB_SZ (192*WLD)            // 199680
#define GAST (64*LD64)             // 9216/stage, 3 stages
#define GRU_SMEM (WB_SZ + 3*GAST)  // 227328

__device__ __forceinline__ void gru_ldA(uint32_t dst, int tid, int b0, int c,
                                        const __half* __restrict__ h16){
    const int k0 = c * 64;
    #pragma unroll
    for (int i = 0; i < 2; i++) {            // 512 u4
        const int q = tid + i * 256;
        const int r = q >> 3, u = q & 7;
        CP16(dst + r * LD64 + u * 16, h16 + (size_t)(b0 + r) * Hdim + k0 + u * 8);
    }
}

__global__ __launch_bounds__(256, 1) void gru_pers(
    const float* __restrict__ bhh, float* __restrict__ outp)
{
    extern __shared__ __align__(16) char smp[];
    const uint32_t sb = smem_u32(smp);
    const uint32_t WB = sb;
    const uint32_t AB = sb + WB_SZ;
    const int tid = threadIdx.x, lane = tid & 31, wid = tid >> 5;
    const int wm = wid >> 2, wn = wid & 3;          // m32 x (3 x 16 j)
    const int bt = blockIdx.x, by = blockIdx.y;
    const int b0 = bt * 64, j0 = by * 64;
    unsigned* const myflag = &g_flag[(bt * 8 + by) * 32];
    const unsigned* const grpflag = &g_flag[bt * 8 * 32];

    // resident Whh: 192 rows x 512 halves
    for (int q = tid; q < 12288; q += 256) {
        const int r = q >> 6, u = q & 63;
        const int g = r >> 6, jj = r & 63;
        uint4 v = *(const uint4*)(g_Whh16 + (size_t)((g << 9) + j0 + jj) * Hdim + u * 8);
        STS16(WB + r * WLD + u * 16, v);
    }
    __syncthreads();

    const uint32_t a_lrow = (lane & 15) * LD64 + (lane >> 4) * 16;
    const uint32_t b_lrowW = ((lane >> 4) * 8 + (lane & 7)) * WLD + ((lane >> 3) & 1) * 16;

    const int jjb = j0 + wn * 16 + (lane & 3) * 2;        // + nfp*8
    const int brow[4] = {
        b0 + wm * 32 + (lane >> 2),
        b0 + wm * 32 + (lane >> 2) + 8,
        b0 + wm * 32 + 16 + (lane >> 2),
        b0 + wm * 32 + 16 + (lane >> 2) + 8
    };

    float2 bhh_r[3][2];
    #pragma unroll
    for (int g = 0; g < 3; g++)
        #pragma unroll
        for (int nfp = 0; nfp < 2; nfp++)
            bhh_r[g][nfp] = *(const float2*)(bhh + g * Hdim + jjb + nfp * 8);

    float hold[4][2][2];
    #pragma unroll
    for (int r4 = 0; r4 < 4; r4++)
        #pragma unroll
        for (int nfp = 0; nfp < 2; nfp++) { hold[r4][nfp][0] = 0.0f; hold[r4][nfp][1] = 0.0f; }

    for (int s = 0; s < Sdim; s++) {
        const int par = s & 1;
        const __half* __restrict__ h16 = g_h16[par];
        const unsigned us = (unsigned)s;

        float acc[2][3][2][4];
        #pragma unroll
        for (int mf = 0; mf < 2; mf++)
            #pragma unroll
            for (int g = 0; g < 3; g++)
                #pragma unroll
                for (int nfp = 0; nfp < 2; nfp++)
                    #pragma unroll
                    for (int d = 0; d < 4; d++) acc[mf][g][nfp][d] = 0.0f;

        // gate first two chunk loads on their producers (tid0 polls, bar broadcasts)
        if (tid == 0) { wait_flag(grpflag + 0 * 32, us); wait_flag(grpflag + 1 * 32, us); }
        __syncthreads();
        gru_ldA(AB, tid, b0, 0, h16); CP_COMMIT();
        gru_ldA(AB + GAST, tid, b0, 1, h16); CP_COMMIT();

        // epilogue operands (independent of h) — hidden behind MMA
        float gate[4];
        #pragma unroll
        for (int r4 = 0; r4 < 4; r4++) gate[r4] = g_G[s * Bdim + brow[r4]];
        __half2 xgp[4][3][2];
        #pragma unroll
        for (int r4 = 0; r4 < 4; r4++) {
            const __half* xrow = g_xg16 + ((size_t)s * Bdim + brow[r4]) * H3;
            #pragma unroll
            for (int g = 0; g < 3; g++)
                #pragma unroll
                for (int nfp = 0; nfp < 2; nfp++)
                    xgp[r4][g][nfp] = *(const __half2*)(xrow + g * Hdim + jjb + nfp * 8);
        }

        for (int c = 0; c < 8; c++) {
            // poll next producer BEFORE the barrier so the bar broadcasts it
            if (tid == 0 && c + 2 < 8) wait_flag(grpflag + (c + 2) * 32, us);
            CP_WAIT1();
            __syncthreads();
            if (c + 2 < 8) gru_ldA(AB + ((c + 2) % 3) * GAST, tid, b0, c + 2, h16);
            CP_COMMIT();
            const uint32_t cur = AB + (c % 3) * GAST;
            const uint32_t koff = c * 128;
            #pragma unroll
            for (int kk = 0; kk < 4; kk++) {
                uint32_t a[2][4];
                #pragma unroll
                for (int mf = 0; mf < 2; mf++)
                    LDSM4(a[mf][0], a[mf][1], a[mf][2], a[mf][3],
                          cur + (wm * 32 + mf * 16) * LD64 + a_lrow + kk * 32);
                #pragma unroll
                for (int g = 0; g < 3; g++) {
                    uint32_t b0r, b1r, b2r, b3r;
                    LDSM4(b0r, b1r, b2r, b3r,
                          WB + (g * 64 + wn * 16) * WLD + koff + kk * 32 + b_lrowW);
                    #pragma unroll
                    for (int mf = 0; mf < 2; mf++) {
                        mma16816(acc[mf][g][0], a[mf][0], a[mf][1], a[mf][2], a[mf][3], b0r, b1r);
                        mma16816(acc[mf][g][1], a[mf][0], a[mf][1], a[mf][2], a[mf][3], b2r, b3r);
                    }
                }
            }
        }

        const int last = (s == Sdim - 1);
        __half* __restrict__ h16N = g_h16[par ^ 1];

        #pragma unroll
        for (int mf = 0; mf < 2; mf++) {
            #pragma unroll
            for (int half = 0; half < 2; half++) {
                const int r4 = mf * 2 + half;
                const int bb = brow[r4];
                const float gt = gate[r4];
                #pragma unroll
                for (int nfp = 0; nfp < 2; nfp++) {
                    float hn2[2];
                    #pragma unroll
                    for (int cc = 0; cc < 2; cc++) {
                        const int ai = half * 2 + cc;
                        const float hr = acc[mf][0][nfp][ai] + (cc ? bhh_r[0][nfp].y : bhh_r[0][nfp].x);
                        const float hz = acc[mf][1][nfp][ai] + (cc ? bhh_r[1][nfp].y : bhh_r[1][nfp].x);
                        const float hnv = acc[mf][2][nfp][ai] + (cc ? bhh_r[2][nfp].y : bhh_r[2][nfp].x);
                        const float xr = cc ? __high2float(xgp[r4][0][nfp]) : __low2float(xgp[r4][0][nfp]);
                        const float xz = cc ? __high2float(xgp[r4][1][nfp]) : __low2float(xgp[r4][1][nfp]);
                        const float xn = cc ? __high2float(xgp[r4][2][nfp]) : __low2float(xgp[r4][2][nfp]);
                        const float r = sigmoidf_(xr + hr);
                        const float z = sigmoidf_(xz + hz);
                        const float n = tanhf_(xn + r * hnv);
                        const float ho = hold[r4][nfp][cc];
                        const float hnew = gt * ((1.0f - z) * n + z * ho) + (1.0f - gt) * ho;
                        hold[r4][nfp][cc] = hnew;
                        hn2[cc] = hnew;
                    }
                    if (last) {
                        *(float2*)(outp + (size_t)bb * Hdim + jjb + nfp * 8) = make_float2(hn2[0], hn2[1]);
                    } else {
                        *(__half2*)(h16N + (size_t)bb * Hdim + jjb + nfp * 8) = __floats2half2_rn(hn2[0], hn2[1]);
                    }
                }
            }
        }

        if (!last) {
            __syncthreads();                 // all h16N stores issued
            if (tid == 0) {
                __threadfence();             // release h16N before flag
                atomicExch(myflag, us + 1u);
            }
        }
    }
}

// ---------------------------------------------------------------------------
extern "C" void kernel_launch(void* const* d_in, const int* in_sizes, int n_in,
                              void* d_out, int out_size)
{
    const float* C    = (const float*)d_in[0];
    const float* Q    = (const float*)d_in[1];
    const float* PM   = (const float*)d_in[2];
    const float* fc1w = (const float*)d_in[3];
    const float* fc1b = (const float*)d_in[4];
    const float* fc2w = (const float*)d_in[5];
    const float* fc2b = (const float*)d_in[6];
    const float* Wih  = (const float*)d_in[7];
    const float* Whh  = (const float*)d_in[8];
    const float* bih  = (const float*)d_in[9];
    const float* bhh  = (const float*)d_in[10];
    float* out = (float*)d_out;

    static int configured = 0;
    if (!configured) {
        cudaFuncSetAttribute(G_mma,    cudaFuncAttributeMaxDynamicSharedMemorySize, 2 * GST3);
        cudaFuncSetAttribute(xg_mma,   cudaFuncAttributeMaxDynamicSharedMemorySize, 4 * XST);
        cudaFuncSetAttribute(gru_pers, cudaFuncAttributeMaxDynamicSharedMemorySize, GRU_SMEM);
        configured = 1;
    }

    zero_init_kernel<<<(Bdim*Hdim + 255)/256, 256>>>();
    cvt_C16_kernel<<<32768, 256>>>(C);
    cvt_W16_kernel<<<1792, 256>>>(Wih, Whh, fc1w);
    G_mma<<<Mrows/128, 512, 2 * GST3>>>(Q, PM, fc1b, fc2w, fc2b);
    xg_mma<<<dim3(Mrows/128, H3/256), 512, 4 * XST>>>(bih);
    gru_pers<<<dim3(Bdim/64, Hdim/64), 256, GRU_SMEM>>>(bhh, out);
}

// round 14
// speedup vs baseline: 1.1347x; 1.1347x over previous
#include <cuda_runtime.h>
#include <cuda_fp16.h>
#include <math.h>
#include <stdint.h>

#define Hdim 512
#define SHdim 120
#define Bdim 1024
#define Sdim 64
#define H3 1536
#define H4 2048
#define Mrows (Bdim*Sdim)
#define LD 80          // 32-half (64B) rows + 16B pad
#define LD64 144       // 64-half (128B) rows + 16B pad
#define WLD 1040       // resident rows: 512 halves (1024B) + 16B pad

// ----------------------------- device scratch ------------------------------
__device__ float g_G[Sdim*Bdim];
__device__ __half g_xg16[(size_t)Sdim*Bdim*H3];      // xg in fp16
__device__ __half g_h16[2][Bdim*Hdim];               // fp16 MMA operand image
__device__ __half g_C16[(size_t)Mrows*Hdim];         // C fp16
__device__ __half g_Wih16[H3*Hdim];
__device__ __half g_Whh16[H3*Hdim];
__device__ __half g_fc1w16[128*H4];
__device__ unsigned g_grp_cnt[16*32];                // per-b-tile barrier (128B stride)
__device__ unsigned g_grp_gen[16*32];

// fast transcendentals: rel err ~1e-6 — far below fp16 noise
__device__ __forceinline__ float sigmoidf_(float x){
    return __fdividef(1.0f, 1.0f + __expf(-x));
}
__device__ __forceinline__ float tanhf_(float x){
    return __fdividef(2.0f, 1.0f + __expf(-2.0f * x)) - 1.0f;
}

// ----------------------------- asm helpers ---------------------------------
__device__ __forceinline__ uint32_t smem_u32(const void* p){
    uint32_t a;
    asm("{ .reg .u64 t; cvta.to.shared.u64 t, %1; cvt.u32.u64 %0, t; }" : "=r"(a) : "l"(p));
    return a;
}
__device__ __forceinline__ void mma16816(float* c, uint32_t a0, uint32_t a1,
                                         uint32_t a2, uint32_t a3,
                                         uint32_t b0, uint32_t b1){
    asm volatile(
        "mma.sync.aligned.m16n8k16.row.col.f32.f16.f16.f32 "
        "{%0,%1,%2,%3},{%4,%5,%6,%7},{%8,%9},{%0,%1,%2,%3};"
        : "+f"(c[0]), "+f"(c[1]), "+f"(c[2]), "+f"(c[3])
        : "r"(a0), "r"(a1), "r"(a2), "r"(a3), "r"(b0), "r"(b1));
}
#define LDSM4(r0,r1,r2,r3, addr) \
    asm volatile("ldmatrix.sync.aligned.m8n8.x4.shared.b16 {%0,%1,%2,%3}, [%4];" \
        : "=r"(r0), "=r"(r1), "=r"(r2), "=r"(r3) : "r"(addr))
#define STS16(dst, v) asm volatile("st.shared.v4.b32 [%0],{%1,%2,%3,%4};" \
        :: "r"(dst), "r"((v).x), "r"((v).y), "r"((v).z), "r"((v).w))
#define CP16(dst, src) asm volatile("cp.async.cg.shared.global [%0], [%1], 16;" \
        :: "r"(dst), "l"(src))
#define CP_COMMIT() asm volatile("cp.async.commit_group;" ::: "memory")
#define CP_WAIT0()  asm volatile("cp.async.wait_group 0;" ::: "memory")
#define CP_WAIT1()  asm volatile("cp.async.wait_group 1;" ::: "memory")

// ----------------------------- init / convert ------------------------------
__global__ void zero_init_kernel(){
    int i = blockIdx.x * blockDim.x + threadIdx.x;
    if (i < Bdim * Hdim) g_h16[0][i] = __float2half_rn(0.0f);
    if (i < 16*32) { g_grp_cnt[i] = 0u; g_grp_gen[i] = 0u; }
}
__device__ __forceinline__ uint2 cvt4h(float4 v){
    __half2 h0(__float2half_rn(v.x), __float2half_rn(v.y));
    __half2 h1(__float2half_rn(v.z), __float2half_rn(v.w));
    uint2 o; o.x = *(uint32_t*)&h0; o.y = *(uint32_t*)&h1; return o;
}
__global__ void cvt_C16_kernel(const float* __restrict__ src){
    size_t i = (size_t)blockIdx.x * blockDim.x + threadIdx.x;   // 8388608 float4
    ((uint2*)g_C16)[i] = cvt4h(((const float4*)src)[i]);
}
__global__ void cvt_W16_kernel(const float* __restrict__ wih,
                               const float* __restrict__ whh,
                               const float* __restrict__ fc1w){
    int i = blockIdx.x * blockDim.x + threadIdx.x;
    const int nW = H3 * Hdim / 4;                    // 196608
    const int nF = SHdim * H4 / 4;                   // 61440
    if (i < nW) {
        ((uint2*)g_Wih16)[i] = cvt4h(((const float4*)wih)[i]);
    } else if (i < 2*nW) {
        int j = i - nW;
        ((uint2*)g_Whh16)[j] = cvt4h(((const float4*)whh)[j]);
    } else if (i < 2*nW + nF) {
        int j = i - 2*nW;
        ((uint2*)g_fc1w16)[j] = cvt4h(((const float4*)fc1w)[j]);
    } else {
        int j = i - 2*nW - nF;                       // 4096 pad uint2
        ((uint2*)g_fc1w16)[nF + j] = make_uint2(0u, 0u);
    }
}

// ---------------------------------------------------------------------------
// Gate network: one C16 read per chunk feeds all 4 feat parts.
// CTA m128 x n128 (120 real), 512 threads; warps 4m x 4n; 16 chunks k32.
// ---------------------------------------------------------------------------
#define GAp (128*LD)               // 10240 per part image
#define GA4 (4*GAp)                // 40960 A block (4 parts)
#define GST3 (GA4 + 4*GAp)         // stage = A(4) + B(4) = 81920

__global__ __launch_bounds__(512, 1) void G_mma(
    const float* __restrict__ Q, const float* __restrict__ PM,
    const float* __restrict__ fc1b, const float* __restrict__ fc2w,
    const float* __restrict__ fc2b)
{
    extern __shared__ __align__(16) char smg2[];
    __shared__ __align__(16) float sQP[2][2][Hdim];   // [q/pm][b_local][k]
    __shared__ __align__(16) float red[4][128];       // fc2 cross-warp partials
    const uint32_t sb = smem_u32(smg2);
    const int tid = threadIdx.x, lane = tid & 31, wid = tid >> 5;
    const int wm = wid >> 2, wn = wid & 3;            // 4m x 4n, warp m32 x n32
    const int m0 = blockIdx.x * 128;

    {
        const int b_base = m0 >> 6;
        for (int q = tid; q < 2 * Hdim / 4; q += 512) {
            const int bl = q / (Hdim/4), u = q % (Hdim/4);
            *(float4*)&sQP[0][bl][u*4] = *(const float4*)(Q  + (size_t)(b_base+bl)*Hdim + u*4);
            *(float4*)&sQP[1][bl][u*4] = *(const float4*)(PM + (size_t)(b_base+bl)*Hdim + u*4);
        }
    }
    __syncthreads();

    float acc[2][4][4];                               // [mf][nb][frag]
    #pragma unroll
    for (int mf = 0; mf < 2; mf++)
        #pragma unroll
        for (int nb = 0; nb < 4; nb++)
            #pragma unroll
            for (int d = 0; d < 4; d++) acc[mf][nb][d] = 0.0f;

    auto G_fetchC = [&](int c, uint4* rr) {
        const int base0 = c * 32;                     // 512 u4, one per thread
        const int r = tid >> 2, u = tid & 3;
        rr[0] = *(const uint4*)(g_C16 + (size_t)(m0 + r) * Hdim + base0 + u * 8);
    };
    auto G_storeA = [&](int c, uint32_t buf, const uint4* rr) {
        const int base0 = c * 32;
        const int r = tid >> 2, u = tid & 3;
        const __half* ch = (const __half*)&rr[0];
        float cf[8];
        #pragma unroll
        for (int j = 0; j < 8; j++) cf[j] = __half2float(ch[j]);
        const float* qv = &sQP[0][r >> 6][base0 + u * 8];
        const float* pv = &sQP[1][r >> 6][base0 + u * 8];
        #pragma unroll
        for (int part = 0; part < 4; part++) {
            const float* vv = (part & 1) ? pv : qv;
            uint32_t o[4];
            #pragma unroll
            for (int j = 0; j < 4; j++) {
                const float x0 = (part < 2) ? cf[2*j]   * vv[2*j]
                                            : fabsf(cf[2*j]   - vv[2*j]);
                const float x1 = (part < 2) ? cf[2*j+1] * vv[2*j+1]
                                            : fabsf(cf[2*j+1] - vv[2*j+1]);
                const __half2 hh = __floats2half2_rn(x0, x1);
                o[j] = *(const uint32_t*)&hh;
            }
            const uint4 v4 = make_uint4(o[0], o[1], o[2], o[3]);
            STS16(buf + part * GAp + r * LD + u * 16, v4);
        }
    };
    auto G_cpB = [&](int c, uint32_t buf) {
        const int base0 = c * 32;
        #pragma unroll
        for (int i = 0; i < 4; i++) {               // 2048 u4 (4 parts x 512)
            const int q = tid + i * 512;
            const int part = q >> 9, rem = q & 511;
            const int r = rem >> 2, u = rem & 3;
            CP16(buf + GA4 + part * GAp + r * LD + u * 16,
                 g_fc1w16 + (size_t)r * H4 + part * 512 + base0 + u * 8);
        }
    };

    uint4 rr[1];
    G_fetchC(0, rr);
    G_cpB(0, sb);
    CP_COMMIT();
    G_storeA(0, sb, rr);
    CP_WAIT0();
    __syncthreads();

    const uint32_t a_lane = (lane & 15) * LD + (lane >> 4) * 16;
    const uint32_t b_lane = ((lane >> 4) * 8 + (lane & 7)) * LD + ((lane >> 3) & 1) * 16;

    for (int c = 0; c < 16; c++) {
        const uint32_t cur = sb + (c & 1) * GST3;
        const uint32_t nxt = sb + ((c + 1) & 1) * GST3;
        if (c < 15) {
            G_fetchC(c + 1, rr);
            G_cpB(c + 1, nxt);
        }
        CP_COMMIT();
        #pragma unroll
        for (int part = 0; part < 4; part++) {
            #pragma unroll
            for (int kk = 0; kk < 2; kk++) {
                uint32_t a[2][4];
                #pragma unroll
                for (int mf = 0; mf < 2; mf++)
                    LDSM4(a[mf][0], a[mf][1], a[mf][2], a[mf][3],
                          cur + part * GAp + (wm * 32 + mf * 16) * LD + kk * 32 + a_lane);
                #pragma unroll
                for (int nbp = 0; nbp < 2; nbp++) {
                    uint32_t b0, b1, b2, b3;
                    LDSM4(b0, b1, b2, b3,
                          cur + GA4 + part * GAp + (wn * 32 + nbp * 16) * LD + kk * 32 + b_lane);
                    #pragma unroll
                    for (int mf = 0; mf < 2; mf++) {
                        mma16816(acc[mf][nbp*2],   a[mf][0], a[mf][1], a[mf][2], a[mf][3], b0, b1);
                        mma16816(acc[mf][nbp*2+1], a[mf][0], a[mf][1], a[mf][2], a[mf][3], b2, b3);
                    }
                }
            }
        }
        if (c < 15) G_storeA(c + 1, nxt, rr);
        CP_WAIT0();
        __syncthreads();
    }

    // fc2 epilogue: warp-local tanh+dot over warp's n32, then 4-way wn reduce
    #pragma unroll
    for (int mf = 0; mf < 2; mf++) {
        #pragma unroll
        for (int half = 0; half < 2; half++) {
            float partial = 0.0f;
            #pragma unroll
            for (int nb = 0; nb < 4; nb++) {
                #pragma unroll
                for (int cc = 0; cc < 2; cc++) {
                    const int n = wn * 32 + nb * 8 + (lane & 3) * 2 + cc;
                    if (n < SHdim)
                        partial += fc2w[n] * tanhf_(acc[mf][nb][half*2+cc] + fc1b[n]);
                }
            }
            partial += __shfl_xor_sync(0xffffffffu, partial, 1);
            partial += __shfl_xor_sync(0xffffffffu, partial, 2);
            if ((lane & 3) == 0)
                red[wn][wm * 32 + mf * 16 + half * 8 + (lane >> 2)] = partial;
        }
    }
    __syncthreads();
    if (tid < 128) {
        const int m = m0 + tid;
        g_G[(m & 63) * Bdim + (m >> 6)] =
            sigmoidf_(red[0][tid] + red[1][tid] + red[2][tid] + red[3][tid] + fc2b[0]);
    }
}

// ---------------------------------------------------------------------------
// xg = C @ Wih^T + b (fp16, single term), A-RESIDENT version.
// One CTA per m-tile (128 rows). A (128x512 fp16, 130KB) loaded to smem ONCE;
// loop 6 n-tiles of 256, each with 8 k64 B chunks, 2-stage cp.async B stream.
// Output fp16.
// ---------------------------------------------------------------------------
#define XAW WLD                    // A resident row stride (1040)
#define XA_RES (128*XAW)           // 133120
#define XB64 (256*LD64)            // 36864 per B stage
#define XG_SMEM (XA_RES + 2*XB64)  // 206848

__device__ __forceinline__ void xgB_ld(uint32_t buf, int tid, int t){
    const int n0 = (t >> 3) * 256;
    const int k0 = (t & 7) * 64;
    #pragma unroll
    for (int i = 0; i < 4; i++) {            // 2048 u4 (256 rows x 8)
        const int q = tid + i * 512;
        const int r = q >> 3, u = q & 7;
        CP16(buf + r * LD64 + u * 16, g_Wih16 + (size_t)(n0 + r) * Hdim + k0 + u * 8);
    }
}

__global__ __launch_bounds__(512, 1) void xg_mma(const float* __restrict__ bih)
{
    extern __shared__ __align__(16) char smx[];
    const uint32_t sb = smem_u32(smx);
    const uint32_t A0 = sb, B0 = sb + XA_RES;
    const int tid = threadIdx.x, lane = tid & 31, wid = tid >> 5;
    const int wm = wid >> 3, wn = wid & 7;           // warp m64 x n32
    const int m0 = blockIdx.x * 128;

    // load A resident: 128 rows x 512 halves (8192 u4)
    #pragma unroll
    for (int i = 0; i < 16; i++) {
        const int idx = tid + i * 512;
        const int row = idx >> 6, u = idx & 63;
        CP16(A0 + row * XAW + u * 16, g_C16 + (size_t)(m0 + row) * Hdim + u * 8);
    }
    CP_COMMIT();
    xgB_ld(B0, tid, 0);
    CP_COMMIT();
    CP_WAIT0();
    __syncthreads();

    const uint32_t a_lrow = (lane & 15) * XAW + (lane >> 4) * 16;
    const uint32_t b_lrow = ((lane >> 4) * 8 + (lane & 7)) * LD64 + ((lane >> 3) & 1) * 16;

    for (int nt = 0; nt < 6; nt++) {
        float acc[4][4][4];
        #pragma unroll
        for (int a = 0; a < 4; a++)
            #pragma unroll
            for (int b = 0; b < 4; b++)
                #pragma unroll
                for (int d = 0; d < 4; d++) acc[a][b][d] = 0.0f;

        for (int c = 0; c < 8; c++) {
            const int t = nt * 8 + c;
            if (t + 1 < 48) {
                xgB_ld(B0 + ((t + 1) & 1) * XB64, tid, t + 1);
                CP_COMMIT();
                CP_WAIT1();
            } else {
                CP_WAIT0();
            }
            __syncthreads();                 // B[t] visible to all threads
            const uint32_t curB = B0 + (t & 1) * XB64;
            const uint32_t akoff = c * 128;
            #pragma unroll
            for (int kk = 0; kk < 4; kk++) {
                uint32_t a[4][4];
                #pragma unroll
                for (int mf = 0; mf < 4; mf++)
                    LDSM4(a[mf][0], a[mf][1], a[mf][2], a[mf][3],
                          A0 + (wm * 64 + mf * 16) * XAW + akoff + kk * 32 + a_lrow);
                #pragma unroll
                for (int nfp = 0; nfp < 2; nfp++) {
                    uint32_t b0, b1, b2, b3;
                    LDSM4(b0, b1, b2, b3,
                          curB + (wn * 32 + nfp * 16) * LD64 + kk * 32 + b_lrow);
                    #pragma unroll
                    for (int mf = 0; mf < 4; mf++) {
                        mma16816(acc[mf][nfp*2],   a[mf][0], a[mf][1], a[mf][2], a[mf][3], b0, b1);
                        mma16816(acc[mf][nfp*2+1], a[mf][0], a[mf][1], a[mf][2], a[mf][3], b2, b3);
                    }
                }
            }
            __syncthreads();                 // MMA done before buffer reuse
        }

        // epilogue for this n-tile
        const int n0 = nt * 256;
        #pragma unroll
        for (int mf = 0; mf < 4; mf++) {
            #pragma unroll
            for (int half = 0; half < 2; half++) {
                const int m = m0 + wm * 64 + mf * 16 + (lane >> 2) + half * 8;
                const size_t ob = ((size_t)(m & 63) * Bdim + (m >> 6)) * H3;
                #pragma unroll
                for (int nf = 0; nf < 4; nf++) {
                    const int jj = n0 + wn * 32 + nf * 8 + (lane & 3) * 2;
                    const float ox = acc[mf][nf][half*2+0] + bih[jj];
                    const float oy = acc[mf][nf][half*2+1] + bih[jj+1];
                    *(__half2*)(g_xg16 + ob + jj) = __floats2half2_rn(ox, oy);
                }
            }
        }
    }
}

// ---------------------------------------------------------------------------
// Persistent GRU (R12 known-good): Whh resident; register-carried h;
// per-b-tile 8-CTA barrier with tid0-only poll.
// ---------------------------------------------------------------------------
#define WB_SZ (192*WLD)            // 199680
#define GAST (64*LD64)             // 9216/stage, 3 stages
#define GRU_SMEM (WB_SZ + 3*GAST)  // 227328

__device__ __forceinline__ void gru_ldA(uint32_t dst, int tid, int b0, int c,
                                        const __half* __restrict__ h16){
    const int k0 = c * 64;
    #pragma unroll
    for (int i = 0; i < 2; i++) {            // 512 u4
        const int q = tid + i * 256;
        const int r = q >> 3, u = q & 7;
        CP16(dst + r * LD64 + u * 16, h16 + (size_t)(b0 + r) * Hdim + k0 + u * 8);
    }
}

__global__ __launch_bounds__(256, 1) void gru_pers(
    const float* __restrict__ bhh, float* __restrict__ outp)
{
    extern __shared__ __align__(16) char smp[];
    const uint32_t sb = smem_u32(smp);
    const uint32_t WB = sb;
    const uint32_t AB = sb + WB_SZ;
    const int tid = threadIdx.x, lane = tid & 31, wid = tid >> 5;
    const int wm = wid >> 2, wn = wid & 3;          // m32 x (3 x 16 j)
    const int bt = blockIdx.x;
    const int b0 = bt * 64, j0 = blockIdx.y * 64;
    unsigned* const cnt = &g_grp_cnt[bt * 32];
    unsigned* const gen = &g_grp_gen[bt * 32];

    // resident Whh: 192 rows x 512 halves
    for (int q = tid; q < 12288; q += 256) {
        const int r = q >> 6, u = q & 63;
        const int g = r >> 6, jj = r & 63;
        uint4 v = *(const uint4*)(g_Whh16 + (size_t)((g << 9) + j0 + jj) * Hdim + u * 8);
        STS16(WB + r * WLD + u * 16, v);
    }
    __syncthreads();

    const uint32_t a_lrow = (lane & 15) * LD64 + (lane >> 4) * 16;
    const uint32_t b_lrowW = ((lane >> 4) * 8 + (lane & 7)) * WLD + ((lane >> 3) & 1) * 16;

    const int jjb = j0 + wn * 16 + (lane & 3) * 2;        // + nfp*8
    const int brow[4] = {
        b0 + wm * 32 + (lane >> 2),
        b0 + wm * 32 + (lane >> 2) + 8,
        b0 + wm * 32 + 16 + (lane >> 2),
        b0 + wm * 32 + 16 + (lane >> 2) + 8
    };

    float2 bhh_r[3][2];
    #pragma unroll
    for (int g = 0; g < 3; g++)
        #pragma unroll
        for (int nfp = 0; nfp < 2; nfp++)
            bhh_r[g][nfp] = *(const float2*)(bhh + g * Hdim + jjb + nfp * 8);

    float hold[4][2][2];
    #pragma unroll
    for (int r4 = 0; r4 < 4; r4++)
        #pragma unroll
        for (int nfp = 0; nfp < 2; nfp++) { hold[r4][nfp][0] = 0.0f; hold[r4][nfp][1] = 0.0f; }

    for (int s = 0; s < Sdim; s++) {
        const int par = s & 1;
        const __half* __restrict__ h16 = g_h16[par];

        float acc[2][3][2][4];
        #pragma unroll
        for (int mf = 0; mf < 2; mf++)
            #pragma unroll
            for (int g = 0; g < 3; g++)
                #pragma unroll
                for (int nfp = 0; nfp < 2; nfp++)
                    #pragma unroll
                    for (int d = 0; d < 4; d++) acc[mf][g][nfp][d] = 0.0f;

        gru_ldA(AB, tid, b0, 0, h16); CP_COMMIT();
        gru_ldA(AB + GAST, tid, b0, 1, h16); CP_COMMIT();

        // epilogue operands (independent of h) — hidden behind MMA
        float gate[4];
        #pragma unroll
        for (int r4 = 0; r4 < 4; r4++) gate[r4] = g_G[s * Bdim + brow[r4]];
        __half2 xgp[4][3][2];
        #pragma unroll
        for (int r4 = 0; r4 < 4; r4++) {
            const __half* xrow = g_xg16 + ((size_t)s * Bdim + brow[r4]) * H3;
            #pragma unroll
            for (int g = 0; g < 3; g++)
                #pragma unroll
                for (int nfp = 0; nfp < 2; nfp++)
                    xgp[r4][g][nfp] = *(const __half2*)(xrow + g * Hdim + jjb + nfp * 8);
        }

        for (int c = 0; c < 8; c++) {
            CP_WAIT1();
            __syncthreads();
            if (c + 2 < 8) gru_ldA(AB + ((c + 2) % 3) * GAST, tid, b0, c + 2, h16);
            CP_COMMIT();
            const uint32_t cur = AB + (c % 3) * GAST;
            const uint32_t koff = c * 128;
            #pragma unroll
            for (int kk = 0; kk < 4; kk++) {
                uint32_t a[2][4];
                #pragma unroll
                for (int mf = 0; mf < 2; mf++)
                    LDSM4(a[mf][0], a[mf][1], a[mf][2], a[mf][3],
                          cur + (wm * 32 + mf * 16) * LD64 + a_lrow + kk * 32);
                #pragma unroll
                for (int g = 0; g < 3; g++) {
                    uint32_t b0r, b1r, b2r, b3r;
                    LDSM4(b0r, b1r, b2r, b3r,
                          WB + (g * 64 + wn * 16) * WLD + koff + kk * 32 + b_lrowW);
                    #pragma unroll
                    for (int mf = 0; mf < 2; mf++) {
                        mma16816(acc[mf][g][0], a[mf][0], a[mf][1], a[mf][2], a[mf][3], b0r, b1r);
                        mma16816(acc[mf][g][1], a[mf][0], a[mf][1], a[mf][2], a[mf][3], b2r, b3r);
                    }
                }
            }
        }

        const int last = (s == Sdim - 1);
        __half* __restrict__ h16N = g_h16[par ^ 1];

        #pragma unroll
        for (int mf = 0; mf < 2; mf++) {
            #pragma unroll
            for (int half = 0; half < 2; half++) {
                const int r4 = mf * 2 + half;
                const int bb = brow[r4];
                const float gt = gate[r4];
                #pragma unroll
                for (int nfp = 0; nfp < 2; nfp++) {
                    float hn2[2];
                    #pragma unroll
                    for (int cc = 0; cc < 2; cc++) {
                        const int ai = half * 2 + cc;
                        const float hr = acc[mf][0][nfp][ai] + (cc ? bhh_r[0][nfp].y : bhh_r[0][nfp].x);
                        const float hz = acc[mf][1][nfp][ai] + (cc ? bhh_r[1][nfp].y : bhh_r[1][nfp].x);
                        const float hnv = acc[mf][2][nfp][ai] + (cc ? bhh_r[2][nfp].y : bhh_r[2][nfp].x);
                        const float xr = cc ? __high2float(xgp[r4][0][nfp]) : __low2float(xgp[r4][0][nfp]);
                        const float xz = cc ? __high2float(xgp[r4][1][nfp]) : __low2float(xgp[r4][1][nfp]);
                        const float xn = cc ? __high2float(xgp[r4][2][nfp]) : __low2float(xgp[r4][2][nfp]);
                        const float r = sigmoidf_(xr + hr);
                        const float z = sigmoidf_(xz + hz);
                        const float n = tanhf_(xn + r * hnv);
                        const float ho = hold[r4][nfp][cc];
                        const float hnew = gt * ((1.0f - z) * n + z * ho) + (1.0f - gt) * ho;
                        hold[r4][nfp][cc] = hnew;
                        hn2[cc] = hnew;
                    }
                    if (last) {
                        *(float2*)(outp + (size_t)bb * Hdim + jjb + nfp * 8) = make_float2(hn2[0], hn2[1]);
                    } else {
                        *(__half2*)(h16N + (size_t)bb * Hdim + jjb + nfp * 8) = __floats2half2_rn(hn2[0], hn2[1]);
                    }
                }
            }
        }

        if (!last) {
            __syncthreads();
            if (tid == 0) {
                __threadfence();
                const unsigned target = (unsigned)(s + 1);
                unsigned arr = atomicAdd(cnt, 1u);
                if (arr == 7u) {
                    *cnt = 0u;
                    __threadfence();
                    atomicExch(gen, target);
                } else {
                    unsigned v;
                    do {
                        asm volatile("ld.acquire.gpu.u32 %0, [%1];" : "=r"(v) : "l"(gen));
                    } while (v < target);
                }
            }
            __syncthreads();
        }
    }
}

// ---------------------------------------------------------------------------
extern "C" void kernel_launch(void* const* d_in, const int* in_sizes, int n_in,
                              void* d_out, int out_size)
{
    const float* C    = (const float*)d_in[0];
    const float* Q    = (const float*)d_in[1];
    const float* PM   = (const float*)d_in[2];
    const float* fc1w = (const float*)d_in[3];
    const float* fc1b = (const float*)d_in[4];
    const float* fc2w = (const float*)d_in[5];
    const float* fc2b = (const float*)d_in[6];
    const float* Wih  = (const float*)d_in[7];
    const float* Whh  = (const float*)d_in[8];
    const float* bih  = (const float*)d_in[9];
    const float* bhh  = (const float*)d_in[10];
    float* out = (float*)d_out;

    static int configured = 0;
    if (!configured) {
        cudaFuncSetAttribute(G_mma,    cudaFuncAttributeMaxDynamicSharedMemorySize, 2 * GST3);
        cudaFuncSetAttribute(xg_mma,   cudaFuncAttributeMaxDynamicSharedMemorySize, XG_SMEM);
        cudaFuncSetAttribute(gru_pers, cudaFuncAttributeMaxDynamicSharedMemorySize, GRU_SMEM);
        configured = 1;
    }

    zero_init_kernel<<<(Bdim*Hdim + 255)/256, 256>>>();
    cvt_C16_kernel<<<32768, 256>>>(C);
    cvt_W16_kernel<<<1792, 256>>>(Wih, Whh, fc1w);
    G_mma<<<Mrows/128, 512, 2 * GST3>>>(Q, PM, fc1b, fc2w, fc2b);
    xg_mma<<<Mrows/128, 512, XG_SMEM>>>(bih);
    gru_pers<<<dim3(Bdim/64, Hdim/64), 256, GRU_SMEM>>>(bhh, out);
}

// round 15
// speedup vs baseline: 1.2168x; 1.0723x over previous
#include <cuda_runtime.h>
#include <cuda_fp16.h>
#include <math.h>
#include <stdint.h>

#define Hdim 512
#define SHdim 120
#define Bdim 1024
#define Sdim 64
#define H3 1536
#define H4 2048
#define Mrows (Bdim*Sdim)
#define LD 80          // 32-half (64B) rows + 16B pad
#define LD64 144       // 64-half (128B) rows + 16B pad
#define WLD 1040       // resident rows: 512 halves (1024B) + 16B pad

// ----------------------------- device scratch ------------------------------
__device__ float g_G[Sdim*Bdim];
__device__ __half g_xg16[(size_t)Sdim*Bdim*H3];      // xg in fp16
__device__ __half g_h16[2][Bdim*Hdim];               // fp16 MMA operand image
__device__ __half g_C16[(size_t)Mrows*Hdim];         // C fp16
__device__ __half g_Wih16[H3*Hdim];
__device__ __half g_Whh16[H3*Hdim];
__device__ __half g_fc1w16[128*H4];
__device__ unsigned g_grp_cnt[16*32];                // per-b-tile barrier (128B stride)
__device__ unsigned g_grp_gen[16*32];

// fast transcendentals: rel err ~1e-6 — far below fp16 noise
__device__ __forceinline__ float sigmoidf_(float x){
    return __fdividef(1.0f, 1.0f + __expf(-x));
}
__device__ __forceinline__ float tanhf_(float x){
    return __fdividef(2.0f, 1.0f + __expf(-2.0f * x)) - 1.0f;
}

// ----------------------------- asm helpers ---------------------------------
__device__ __forceinline__ uint32_t smem_u32(const void* p){
    uint32_t a;
    asm("{ .reg .u64 t; cvta.to.shared.u64 t, %1; cvt.u32.u64 %0, t; }" : "=r"(a) : "l"(p));
    return a;
}
__device__ __forceinline__ void mma16816(float* c, uint32_t a0, uint32_t a1,
                                         uint32_t a2, uint32_t a3,
                                         uint32_t b0, uint32_t b1){
    asm volatile(
        "mma.sync.aligned.m16n8k16.row.col.f32.f16.f16.f32 "
        "{%0,%1,%2,%3},{%4,%5,%6,%7},{%8,%9},{%0,%1,%2,%3};"
        : "+f"(c[0]), "+f"(c[1]), "+f"(c[2]), "+f"(c[3])
        : "r"(a0), "r"(a1), "r"(a2), "r"(a3), "r"(b0), "r"(b1));
}
#define LDSM4(r0,r1,r2,r3, addr) \
    asm volatile("ldmatrix.sync.aligned.m8n8.x4.shared.b16 {%0,%1,%2,%3}, [%4];" \
        : "=r"(r0), "=r"(r1), "=r"(r2), "=r"(r3) : "r"(addr))
#define STS16(dst, v) asm volatile("st.shared.v4.b32 [%0],{%1,%2,%3,%4};" \
        :: "r"(dst), "r"((v).x), "r"((v).y), "r"((v).z), "r"((v).w))
#define CP16(dst, src) asm volatile("cp.async.cg.shared.global [%0], [%1], 16;" \
        :: "r"(dst), "l"(src))
#define CP_COMMIT() asm volatile("cp.async.commit_group;" ::: "memory")
#define CP_WAIT0()  asm volatile("cp.async.wait_group 0;" ::: "memory")
#define CP_WAIT1()  asm volatile("cp.async.wait_group 1;" ::: "memory")
#define CP_WAIT2()  asm volatile("cp.async.wait_group 2;" ::: "memory")

__device__ __forceinline__ uint2 cvt4h(float4 v){
    __half2 h0(__float2half_rn(v.x), __float2half_rn(v.y));
    __half2 h1(__float2half_rn(v.z), __float2half_rn(v.w));
    uint2 o; o.x = *(uint32_t*)&h0; o.y = *(uint32_t*)&h1; return o;
}

// ---------------------------------------------------------------------------
// Fused prologue: zero h16/barriers, cvt C->C16, cvt W/fc1w -> fp16.
// ---------------------------------------------------------------------------
#define NC4  8388608                      // C float4 count
#define NW4  196608                       // Wih/Whh float4 count each
#define NF4  61440                        // fc1w float4 count
#define NPAD 4096                         // fc1w pad uint2
#define NH2  131072                       // h16 zero uint2 (4 halves each)
#define PRO_TOTAL (NC4 + 2*NW4 + NF4 + NPAD + NH2 + 512)

__global__ void prologue_kernel(const float* __restrict__ C,
                                const float* __restrict__ wih,
                                const float* __restrict__ whh,
                                const float* __restrict__ fc1w){
    size_t i = (size_t)blockIdx.x * blockDim.x + threadIdx.x;
    if (i < NC4) {
        ((uint2*)g_C16)[i] = cvt4h(((const float4*)C)[i]);
        return;
    }
    i -= NC4;
    if (i < NW4) { ((uint2*)g_Wih16)[i] = cvt4h(((const float4*)wih)[i]); return; }
    i -= NW4;
    if (i < NW4) { ((uint2*)g_Whh16)[i] = cvt4h(((const float4*)whh)[i]); return; }
    i -= NW4;
    if (i < NF4) { ((uint2*)g_fc1w16)[i] = cvt4h(((const float4*)fc1w)[i]); return; }
    i -= NF4;
    if (i < NPAD) { ((uint2*)g_fc1w16)[NF4 + i] = make_uint2(0u, 0u); return; }
    i -= NPAD;
    if (i < NH2) { ((uint2*)g_h16[0])[i] = make_uint2(0u, 0u); return; }
    i -= NH2;
    if (i < 512) {
        if (i < 16*32) { g_grp_cnt[i] = 0u; if (i < 16*32) g_grp_gen[i] = 0u; }
    }
}

// ---------------------------------------------------------------------------
// Merged G + xg kernel. blockIdx.x < 512 -> gate network; else xg GEMM.
// Both 512 threads. Dynamic smem = 4*XST (221184); G uses a prefix of it.
// ---------------------------------------------------------------------------
#define GAp (128*LD)               // 10240 per part image
#define GA4 (4*GAp)                // 40960 A block (4 parts)
#define GST3 (GA4 + 4*GAp)         // stage = A(4) + B(4) = 81920
#define G_SQP_OFF (2*GST3)         // sQP: 2*2*512 floats = 8192 B
#define G_RED_OFF (G_SQP_OFF + 8192) // red: 4*128 floats = 2048 B

#define XA2 (128*LD64)             // 18432
#define XST (XA2 + 256*LD64)       // 55296
#define MERGED_SMEM (4*XST)        // 221184

__device__ void G_body(char* smx,
    const float* __restrict__ Q, const float* __restrict__ PM,
    const float* __restrict__ fc1b, const float* __restrict__ fc2w,
    const float* __restrict__ fc2b)
{
    const uint32_t sb = smem_u32(smx);
    float* const sQPp = (float*)(smx + G_SQP_OFF);    // [sel*2+bl][512]
    float* const redp = (float*)(smx + G_RED_OFF);    // [wn][128]
    const int tid = threadIdx.x, lane = tid & 31, wid = tid >> 5;
    const int wm = wid >> 2, wn = wid & 3;            // 4m x 4n, warp m32 x n32
    const int m0 = blockIdx.x * 128;

    {
        const int b_base = m0 >> 6;
        for (int q = tid; q < 2 * Hdim / 4; q += 512) {
            const int bl = q / (Hdim/4), u = q % (Hdim/4);
            *(float4*)&sQPp[(0*2+bl)*Hdim + u*4] = *(const float4*)(Q  + (size_t)(b_base+bl)*Hdim + u*4);
            *(float4*)&sQPp[(1*2+bl)*Hdim + u*4] = *(const float4*)(PM + (size_t)(b_base+bl)*Hdim + u*4);
        }
    }
    __syncthreads();

    float acc[2][4][4];
    #pragma unroll
    for (int mf = 0; mf < 2; mf++)
        #pragma unroll
        for (int nb = 0; nb < 4; nb++)
            #pragma unroll
            for (int d = 0; d < 4; d++) acc[mf][nb][d] = 0.0f;

    auto G_fetchC = [&](int c, uint4* rr) {
        const int base0 = c * 32;
        const int r = tid >> 2, u = tid & 3;
        rr[0] = *(const uint4*)(g_C16 + (size_t)(m0 + r) * Hdim + base0 + u * 8);
    };
    auto G_storeA = [&](int c, uint32_t buf, const uint4* rr) {
        const int base0 = c * 32;
        const int r = tid >> 2, u = tid & 3;
        const __half* ch = (const __half*)&rr[0];
        float cf[8];
        #pragma unroll
        for (int j = 0; j < 8; j++) cf[j] = __half2float(ch[j]);
        const float* qv = &sQPp[(0*2+(r>>6))*Hdim + base0 + u*8];
        const float* pv = &sQPp[(1*2+(r>>6))*Hdim + base0 + u*8];
        #pragma unroll
        for (int part = 0; part < 4; part++) {
            const float* vv = (part & 1) ? pv : qv;
            uint32_t o[4];
            #pragma unroll
            for (int j = 0; j < 4; j++) {
                const float x0 = (part < 2) ? cf[2*j]   * vv[2*j]
                                            : fabsf(cf[2*j]   - vv[2*j]);
                const float x1 = (part < 2) ? cf[2*j+1] * vv[2*j+1]
                                            : fabsf(cf[2*j+1] - vv[2*j+1]);
                const __half2 hh = __floats2half2_rn(x0, x1);
                o[j] = *(const uint32_t*)&hh;
            }
            const uint4 v4 = make_uint4(o[0], o[1], o[2], o[3]);
            STS16(buf + part * GAp + r * LD + u * 16, v4);
        }
    };
    auto G_cpB = [&](int c, uint32_t buf) {
        const int base0 = c * 32;
        #pragma unroll
        for (int i = 0; i < 4; i++) {
            const int q = tid + i * 512;
            const int part = q >> 9, rem = q & 511;
            const int r = rem >> 2, u = rem & 3;
            CP16(buf + GA4 + part * GAp + r * LD + u * 16,
                 g_fc1w16 + (size_t)r * H4 + part * 512 + base0 + u * 8);
        }
    };

    uint4 rr[1];
    G_fetchC(0, rr);
    G_cpB(0, sb);
    CP_COMMIT();
    G_storeA(0, sb, rr);
    CP_WAIT0();
    __syncthreads();

    const uint32_t a_lane = (lane & 15) * LD + (lane >> 4) * 16;
    const uint32_t b_lane = ((lane >> 4) * 8 + (lane & 7)) * LD + ((lane >> 3) & 1) * 16;

    for (int c = 0; c < 16; c++) {
        const uint32_t cur = sb + (c & 1) * GST3;
        const uint32_t nxt = sb + ((c + 1) & 1) * GST3;
        if (c < 15) {
            G_fetchC(c + 1, rr);
            G_cpB(c + 1, nxt);
        }
        CP_COMMIT();
        #pragma unroll
        for (int part = 0; part < 4; part++) {
            #pragma unroll
            for (int kk = 0; kk < 2; kk++) {
                uint32_t a[2][4];
                #pragma unroll
                for (int mf = 0; mf < 2; mf++)
                    LDSM4(a[mf][0], a[mf][1], a[mf][2], a[mf][3],
                          cur + part * GAp + (wm * 32 + mf * 16) * LD + kk * 32 + a_lane);
                #pragma unroll
                for (int nbp = 0; nbp < 2; nbp++) {
                    uint32_t b0, b1, b2, b3;
                    LDSM4(b0, b1, b2, b3,
                          cur + GA4 + part * GAp + (wn * 32 + nbp * 16) * LD + kk * 32 + b_lane);
                    #pragma unroll
                    for (int mf = 0; mf < 2; mf++) {
                        mma16816(acc[mf][nbp*2],   a[mf][0], a[mf][1], a[mf][2], a[mf][3], b0, b1);
                        mma16816(acc[mf][nbp*2+1], a[mf][0], a[mf][1], a[mf][2], a[mf][3], b2, b3);
                    }
                }
            }
        }
        if (c < 15) G_storeA(c + 1, nxt, rr);
        CP_WAIT0();
        __syncthreads();
    }

    #pragma unroll
    for (int mf = 0; mf < 2; mf++) {
        #pragma unroll
        for (int half = 0; half < 2; half++) {
            float partial = 0.0f;
            #pragma unroll
            for (int nb = 0; nb < 4; nb++) {
                #pragma unroll
                for (int cc = 0; cc < 2; cc++) {
                    const int n = wn * 32 + nb * 8 + (lane & 3) * 2 + cc;
                    if (n < SHdim)
                        partial += fc2w[n] * tanhf_(acc[mf][nb][half*2+cc] + fc1b[n]);
                }
            }
            partial += __shfl_xor_sync(0xffffffffu, partial, 1);
            partial += __shfl_xor_sync(0xffffffffu, partial, 2);
            if ((lane & 3) == 0)
                redp[wn * 128 + wm * 32 + mf * 16 + half * 8 + (lane >> 2)] = partial;
        }
    }
    __syncthreads();
    if (tid < 128) {
        const int m = m0 + tid;
        g_G[(m & 63) * Bdim + (m >> 6)] =
            sigmoidf_(redp[0*128+tid] + redp[1*128+tid] + redp[2*128+tid] + redp[3*128+tid] + fc2b[0]);
    }
}

__device__ __forceinline__ void xg_ld(uint32_t buf, int tid, int m0, int n0, int c){
    const int k0 = c * 64;
    #pragma unroll
    for (int i = 0; i < 2; i++) {
        const int q = tid + i * 512;
        const int r = q >> 3, u = q & 7;
        CP16(buf + r * LD64 + u * 16, g_C16 + (size_t)(m0 + r) * Hdim + k0 + u * 8);
    }
    #pragma unroll
    for (int i = 0; i < 4; i++) {
        const int q = tid + i * 512;
        const int r = q >> 3, u = q & 7;
        CP16(buf + XA2 + r * LD64 + u * 16, g_Wih16 + (size_t)(n0 + r) * Hdim + k0 + u * 8);
    }
}

__device__ void xg_body(char* smx, const float* __restrict__ bih, int idx)
{
    const uint32_t sb = smem_u32(smx);
    const int tid = threadIdx.x, lane = tid & 31, wid = tid >> 5;
    const int wm = wid >> 3, wn = wid & 7;
    const int m0 = (idx % 512) * 128, n0 = (idx / 512) * 256;

    float acc[4][4][4];
    #pragma unroll
    for (int a = 0; a < 4; a++)
        #pragma unroll
        for (int b = 0; b < 4; b++)
            #pragma unroll
            for (int d = 0; d < 4; d++) acc[a][b][d] = 0.0f;

    xg_ld(sb, tid, m0, n0, 0); CP_COMMIT();
    xg_ld(sb + XST, tid, m0, n0, 1); CP_COMMIT();
    xg_ld(sb + 2*XST, tid, m0, n0, 2); CP_COMMIT();

    const uint32_t a_lrow = (lane & 15) * LD64 + (lane >> 4) * 16;
    const uint32_t b_lrow = ((lane >> 4) * 8 + (lane & 7)) * LD64 + ((lane >> 3) & 1) * 16;

    for (int c = 0; c < 8; c++) {
        CP_WAIT2();
        __syncthreads();
        if (c + 3 < 8) xg_ld(sb + ((c + 3) & 3) * XST, tid, m0, n0, c + 3);
        CP_COMMIT();
        const uint32_t cur = sb + (c & 3) * XST;
        #pragma unroll
        for (int kk = 0; kk < 4; kk++) {
            uint32_t a[4][4];
            #pragma unroll
            for (int mf = 0; mf < 4; mf++)
                LDSM4(a[mf][0], a[mf][1], a[mf][2], a[mf][3],
                      cur + (wm * 64 + mf * 16) * LD64 + kk * 32 + a_lrow);
            #pragma unroll
            for (int nfp = 0; nfp < 2; nfp++) {
                uint32_t b0, b1, b2, b3;
                LDSM4(b0, b1, b2, b3,
                      cur + XA2 + (wn * 32 + nfp * 16) * LD64 + kk * 32 + b_lrow);
                #pragma unroll
                for (int mf = 0; mf < 4; mf++) {
                    mma16816(acc[mf][nfp*2],   a[mf][0], a[mf][1], a[mf][2], a[mf][3], b0, b1);
                    mma16816(acc[mf][nfp*2+1], a[mf][0], a[mf][1], a[mf][2], a[mf][3], b2, b3);
                }
            }
        }
    }

    #pragma unroll
    for (int mf = 0; mf < 4; mf++) {
        #pragma unroll
        for (int half = 0; half < 2; half++) {
            const int m = m0 + wm * 64 + mf * 16 + (lane >> 2) + half * 8;
            const size_t ob = ((size_t)(m & 63) * Bdim + (m >> 6)) * H3;
            #pragma unroll
            for (int nf = 0; nf < 4; nf++) {
                const int jj = n0 + wn * 32 + nf * 8 + (lane & 3) * 2;
                const float ox = acc[mf][nf][half*2+0] + bih[jj];
                const float oy = acc[mf][nf][half*2+1] + bih[jj+1];
                *(__half2*)(g_xg16 + ob + jj) = __floats2half2_rn(ox, oy);
            }
        }
    }
}

__global__ __launch_bounds__(512, 1) void Gxg_mma(
    const float* __restrict__ Q, const float* __restrict__ PM,
    const float* __restrict__ fc1b, const float* __restrict__ fc2w,
    const float* __restrict__ fc2b, const float* __restrict__ bih)
{
    extern __shared__ __align__(16) char smx[];
    if (blockIdx.x < 512) {
        G_body(smx, Q, PM, fc1b, fc2w, fc2b);
    } else {
        xg_body(smx, bih, blockIdx.x - 512);
    }
}

// ---------------------------------------------------------------------------
// Persistent GRU (R12 known-good): Whh resident; register-carried h;
// per-b-tile 8-CTA barrier with tid0-only poll.
// ---------------------------------------------------------------------------
#define WB_SZ (192*WLD)            // 199680
#define GAST (64*LD64)             // 9216/stage, 3 stages
#define GRU_SMEM (WB_SZ + 3*GAST)  // 227328

__device__ __forceinline__ void gru_ldA(uint32_t dst, int tid, int b0, int c,
                                        const __half* __restrict__ h16){
    const int k0 = c * 64;
    #pragma unroll
    for (int i = 0; i < 2; i++) {
        const int q = tid + i * 256;
        const int r = q >> 3, u = q & 7;
        CP16(dst + r * LD64 + u * 16, h16 + (size_t)(b0 + r) * Hdim + k0 + u * 8);
    }
}

__global__ __launch_bounds__(256, 1) void gru_pers(
    const float* __restrict__ bhh, float* __restrict__ outp)
{
    extern __shared__ __align__(16) char smp[];
    const uint32_t sb = smem_u32(smp);
    const uint32_t WB = sb;
    const uint32_t AB = sb + WB_SZ;
    const int tid = threadIdx.x, lane = tid & 31, wid = tid >> 5;
    const int wm = wid >> 2, wn = wid & 3;          // m32 x (3 x 16 j)
    const int bt = blockIdx.x;
    const int b0 = bt * 64, j0 = blockIdx.y * 64;
    unsigned* const cnt = &g_grp_cnt[bt * 32];
    unsigned* const gen = &g_grp_gen[bt * 32];

    for (int q = tid; q < 12288; q += 256) {
        const int r = q >> 6, u = q & 63;
        const int g = r >> 6, jj = r & 63;
        uint4 v = *(const uint4*)(g_Whh16 + (size_t)((g << 9) + j0 + jj) * Hdim + u * 8);
        STS16(WB + r * WLD + u * 16, v);
    }
    __syncthreads();

    const uint32_t a_lrow = (lane & 15) * LD64 + (lane >> 4) * 16;
    const uint32_t b_lrowW = ((lane >> 4) * 8 + (lane & 7)) * WLD + ((lane >> 3) & 1) * 16;

    const int jjb = j0 + wn * 16 + (lane & 3) * 2;
    const int brow[4] = {
        b0 + wm * 32 + (lane >> 2),
        b0 + wm * 32 + (lane >> 2) + 8,
        b0 + wm * 32 + 16 + (lane >> 2),
        b0 + wm * 32 + 16 + (lane >> 2) + 8
    };

    float2 bhh_r[3][2];
    #pragma unroll
    for (int g = 0; g < 3; g++)
        #pragma unroll
        for (int nfp = 0; nfp < 2; nfp++)
            bhh_r[g][nfp] = *(const float2*)(bhh + g * Hdim + jjb + nfp * 8);

    float hold[4][2][2];
    #pragma unroll
    for (int r4 = 0; r4 < 4; r4++)
        #pragma unroll
        for (int nfp = 0; nfp < 2; nfp++) { hold[r4][nfp][0] = 0.0f; hold[r4][nfp][1] = 0.0f; }

    for (int s = 0; s < Sdim; s++) {
        const int par = s & 1;
        const __half* __restrict__ h16 = g_h16[par];

        float acc[2][3][2][4];
        #pragma unroll
        for (int mf = 0; mf < 2; mf++)
            #pragma unroll
            for (int g = 0; g < 3; g++)
                #pragma unroll
                for (int nfp = 0; nfp < 2; nfp++)
                    #pragma unroll
                    for (int d = 0; d < 4; d++) acc[mf][g][nfp][d] = 0.0f;

        gru_ldA(AB, tid, b0, 0, h16); CP_COMMIT();
        gru_ldA(AB + GAST, tid, b0, 1, h16); CP_COMMIT();

        float gate[4];
        #pragma unroll
        for (int r4 = 0; r4 < 4; r4++) gate[r4] = g_G[s * Bdim + brow[r4]];
        __half2 xgp[4][3][2];
        #pragma unroll
        for (int r4 = 0; r4 < 4; r4++) {
            const __half* xrow = g_xg16 + ((size_t)s * Bdim + brow[r4]) * H3;
            #pragma unroll
            for (int g = 0; g < 3; g++)
                #pragma unroll
                for (int nfp = 0; nfp < 2; nfp++)
                    xgp[r4][g][nfp] = *(const __half2*)(xrow + g * Hdim + jjb + nfp * 8);
        }

        for (int c = 0; c < 8; c++) {
            CP_WAIT1();
            __syncthreads();
            if (c + 2 < 8) gru_ldA(AB + ((c + 2) % 3) * GAST, tid, b0, c + 2, h16);
            CP_COMMIT();
            const uint32_t cur = AB + (c % 3) * GAST;
            const uint32_t koff = c * 128;
            #pragma unroll
            for (int kk = 0; kk < 4; kk++) {
                uint32_t a[2][4];
                #pragma unroll
                for (int mf = 0; mf < 2; mf++)
                    LDSM4(a[mf][0], a[mf][1], a[mf][2], a[mf][3],
                          cur + (wm * 32 + mf * 16) * LD64 + a_lrow + kk * 32);
                #pragma unroll
                for (int g = 0; g < 3; g++) {
                    uint32_t b0r, b1r, b2r, b3r;
                    LDSM4(b0r, b1r, b2r, b3r,
                          WB + (g * 64 + wn * 16) * WLD + koff + kk * 32 + b_lrowW);
                    #pragma unroll
                    for (int mf = 0; mf < 2; mf++) {
                        mma16816(acc[mf][g][0], a[mf][0], a[mf][1], a[mf][2], a[mf][3], b0r, b1r);
                        mma16816(acc[mf][g][1], a[mf][0], a[mf][1], a[mf][2], a[mf][3], b2r, b3r);
                    }
                }
            }
        }

        const int last = (s == Sdim - 1);
        __half* __restrict__ h16N = g_h16[par ^ 1];

        #pragma unroll
        for (int mf = 0; mf < 2; mf++) {
            #pragma unroll
            for (int half = 0; half < 2; half++) {
                const int r4 = mf * 2 + half;
                const int bb = brow[r4];
                const float gt = gate[r4];
                #pragma unroll
                for (int nfp = 0; nfp < 2; nfp++) {
                    float hn2[2];
                    #pragma unroll
                    for (int cc = 0; cc < 2; cc++) {
                        const int ai = half * 2 + cc;
                        const float hr = acc[mf][0][nfp][ai] + (cc ? bhh_r[0][nfp].y : bhh_r[0][nfp].x);
                        const float hz = acc[mf][1][nfp][ai] + (cc ? bhh_r[1][nfp].y : bhh_r[1][nfp].x);
                        const float hnv = acc[mf][2][nfp][ai] + (cc ? bhh_r[2][nfp].y : bhh_r[2][nfp].x);
                        const float xr = cc ? __high2float(xgp[r4][0][nfp]) : __low2float(xgp[r4][0][nfp]);
                        const float xz = cc ? __high2float(xgp[r4][1][nfp]) : __low2float(xgp[r4][1][nfp]);
                        const float xn = cc ? __high2float(xgp[r4][2][nfp]) : __low2float(xgp[r4][2][nfp]);
                        const float r = sigmoidf_(xr + hr);
                        const float z = sigmoidf_(xz + hz);
                        const float n = tanhf_(xn + r * hnv);
                        const float ho = hold[r4][nfp][cc];
                        const float hnew = gt * ((1.0f - z) * n + z * ho) + (1.0f - gt) * ho;
                        hold[r4][nfp][cc] = hnew;
                        hn2[cc] = hnew;
                    }
                    if (last) {
                        *(float2*)(outp + (size_t)bb * Hdim + jjb + nfp * 8) = make_float2(hn2[0], hn2[1]);
                    } else {
                        *(__half2*)(h16N + (size_t)bb * Hdim + jjb + nfp * 8) = __floats2half2_rn(hn2[0], hn2[1]);
                    }
                }
            }
        }

        if (!last) {
            __syncthreads();
            if (tid == 0) {
                __threadfence();
                const unsigned target = (unsigned)(s + 1);
                unsigned arr = atomicAdd(cnt, 1u);
                if (arr == 7u) {
                    *cnt = 0u;
                    __threadfence();
                    atomicExch(gen, target);
                } else {
                    unsigned v;
                    do {
                        asm volatile("ld.acquire.gpu.u32 %0, [%1];" : "=r"(v) : "l"(gen));
                    } while (v < target);
                }
            }
            __syncthreads();
        }
    }
}

// ---------------------------------------------------------------------------
extern "C" void kernel_launch(void* const* d_in, const int* in_sizes, int n_in,
                              void* d_out, int out_size)
{
    const float* C    = (const float*)d_in[0];
    const float* Q    = (const float*)d_in[1];
    const float* PM   = (const float*)d_in[2];
    const float* fc1w = (const float*)d_in[3];
    const float* fc1b = (const float*)d_in[4];
    const float* fc2w = (const float*)d_in[5];
    const float* fc2b = (const float*)d_in[6];
    const float* Wih  = (const float*)d_in[7];
    const float* Whh  = (const float*)d_in[8];
    const float* bih  = (const float*)d_in[9];
    const float* bhh  = (const float*)d_in[10];
    float* out = (float*)d_out;

    static int configured = 0;
    if (!configured) {
        cudaFuncSetAttribute(Gxg_mma,  cudaFuncAttributeMaxDynamicSharedMemorySize, MERGED_SMEM);
        cudaFuncSetAttribute(gru_pers, cudaFuncAttributeMaxDynamicSharedMemorySize, GRU_SMEM);
        configured = 1;
    }

    prologue_kernel<<<(PRO_TOTAL + 255) / 256, 256>>>(C, Wih, Whh, fc1w);
    Gxg_mma<<<512 + 3072, 512, MERGED_SMEM>>>(Q, PM, fc1b, fc2w, fc2b, bih);
    gru_pers<<<dim3(Bdim/64, Hdim/64), 256, GRU_SMEM>>>(bhh, out);
}

// round 17
// speedup vs baseline: 1.2580x; 1.0339x over previous
#include <cuda_runtime.h>
#include <cuda_fp16.h>
#include <math.h>
#include <stdint.h>

#define Hdim 512
#define SHdim 120
#define Bdim 1024
#define Sdim 64
#define H3 1536
#define H4 2048
#define Mrows (Bdim*Sdim)
#define LD 80          // 32-half (64B) rows + 16B pad
#define LD64 144       // 64-half (128B) rows + 16B pad
#define WLD 1040       // resident rows: 512 halves (1024B) + 16B pad

// ----------------------------- device scratch ------------------------------
__device__ float g_G[Sdim*Bdim];
__device__ __half g_xg16[(size_t)Sdim*Bdim*H3];      // xg in fp16
__device__ __half g_h16[2][Bdim*Hdim];               // fp16 MMA operand image
__device__ __half g_C16[(size_t)Mrows*Hdim];         // C fp16
__device__ __half g_Wih16[H3*Hdim];
__device__ __half g_Whh16[H3*Hdim];
__device__ __half g_fc1w16[128*H4];
__device__ unsigned g_grp_cnt[16*32];                // per-b-tile monotonic counter

// fast transcendentals: rel err ~1e-6 — far below fp16 noise
__device__ __forceinline__ float sigmoidf_(float x){
    return __fdividef(1.0f, 1.0f + __expf(-x));
}
__device__ __forceinline__ float tanhf_(float x){
    return __fdividef(2.0f, 1.0f + __expf(-2.0f * x)) - 1.0f;
}

// ----------------------------- asm helpers ---------------------------------
__device__ __forceinline__ uint32_t smem_u32(const void* p){
    uint32_t a;
    asm("{ .reg .u64 t; cvta.to.shared.u64 t, %1; cvt.u32.u64 %0, t; }" : "=r"(a) : "l"(p));
    return a;
}
__device__ __forceinline__ void mma16816(float* c, uint32_t a0, uint32_t a1,
                                         uint32_t a2, uint32_t a3,
                                         uint32_t b0, uint32_t b1){
    asm volatile(
        "mma.sync.aligned.m16n8k16.row.col.f32.f16.f16.f32 "
        "{%0,%1,%2,%3},{%4,%5,%6,%7},{%8,%9},{%0,%1,%2,%3};"
        : "+f"(c[0]), "+f"(c[1]), "+f"(c[2]), "+f"(c[3])
        : "r"(a0), "r"(a1), "r"(a2), "r"(a3), "r"(b0), "r"(b1));
}
#define LDSM4(r0,r1,r2,r3, addr) \
    asm volatile("ldmatrix.sync.aligned.m8n8.x4.shared.b16 {%0,%1,%2,%3}, [%4];" \
        : "=r"(r0), "=r"(r1), "=r"(r2), "=r"(r3) : "r"(addr))
#define STS16(dst, v) asm volatile("st.shared.v4.b32 [%0],{%1,%2,%3,%4};" \
        :: "r"(dst), "r"((v).x), "r"((v).y), "r"((v).z), "r"((v).w))
#define CP16(dst, src) asm volatile("cp.async.cg.shared.global [%0], [%1], 16;" \
        :: "r"(dst), "l"(src))
#define CP_COMMIT() asm volatile("cp.async.commit_group;" ::: "memory")
#define CP_WAIT0()  asm volatile("cp.async.wait_group 0;" ::: "memory")
#define CP_WAIT1()  asm volatile("cp.async.wait_group 1;" ::: "memory")
#define CP_WAIT2()  asm volatile("cp.async.wait_group 2;" ::: "memory")

__device__ __forceinline__ uint2 cvt4h(float4 v){
    __half2 h0(__float2half_rn(v.x), __float2half_rn(v.y));
    __half2 h1(__float2half_rn(v.z), __float2half_rn(v.w));
    uint2 o; o.x = *(uint32_t*)&h0; o.y = *(uint32_t*)&h1; return o;
}

// ---------------------------------------------------------------------------
// Fused prologue: zero h16/counters, cvt C->C16, cvt W/fc1w -> fp16.
// ---------------------------------------------------------------------------
#define NC4  8388608
#define NW4  196608
#define NF4  61440
#define NPAD 4096
#define NH2  131072
#define PRO_TOTAL (NC4 + 2*NW4 + NF4 + NPAD + NH2 + 512)

__global__ void prologue_kernel(const float* __restrict__ C,
                                const float* __restrict__ wih,
                                const float* __restrict__ whh,
                                const float* __restrict__ fc1w){
    size_t i = (size_t)blockIdx.x * blockDim.x + threadIdx.x;
    if (i < NC4) {
        ((uint2*)g_C16)[i] = cvt4h(((const float4*)C)[i]);
        return;
    }
    i -= NC4;
    if (i < NW4) { ((uint2*)g_Wih16)[i] = cvt4h(((const float4*)wih)[i]); return; }
    i -= NW4;
    if (i < NW4) { ((uint2*)g_Whh16)[i] = cvt4h(((const float4*)whh)[i]); return; }
    i -= NW4;
    if (i < NF4) { ((uint2*)g_fc1w16)[i] = cvt4h(((const float4*)fc1w)[i]); return; }
    i -= NF4;
    if (i < NPAD) { ((uint2*)g_fc1w16)[NF4 + i] = make_uint2(0u, 0u); return; }
    i -= NPAD;
    if (i < NH2) { ((uint2*)g_h16[0])[i] = make_uint2(0u, 0u); return; }
    i -= NH2;
    if (i < 16*32) g_grp_cnt[i] = 0u;
}

// ---------------------------------------------------------------------------
// Merged G + xg kernel. blockIdx.x < 512 -> gate network; else xg GEMM
// (n-fastest mapping: consecutive CTAs share the same A m-tile).
// ---------------------------------------------------------------------------
#define GAp (128*LD)               // 10240 per part image
#define GA4 (4*GAp)                // 40960 A block (4 parts)
#define GST3 (GA4 + 4*GAp)         // stage = A(4) + B(4) = 81920
#define G_SQP_OFF (2*GST3)
#define G_RED_OFF (G_SQP_OFF + 8192)

#define XA2 (128*LD64)             // 18432
#define XST (XA2 + 256*LD64)       // 55296
#define MERGED_SMEM (4*XST)        // 221184

__device__ void G_body(char* smx,
    const float* __restrict__ Q, const float* __restrict__ PM,
    const float* __restrict__ fc1b, const float* __restrict__ fc2w,
    const float* __restrict__ fc2b)
{
    const uint32_t sb = smem_u32(smx);
    float* const sQPp = (float*)(smx + G_SQP_OFF);
    float* const redp = (float*)(smx + G_RED_OFF);
    const int tid = threadIdx.x, lane = tid & 31, wid = tid >> 5;
    const int wm = wid >> 2, wn = wid & 3;
    const int m0 = blockIdx.x * 128;

    {
        const int b_base = m0 >> 6;
        for (int q = tid; q < 2 * Hdim / 4; q += 512) {
            const int bl = q / (Hdim/4), u = q % (Hdim/4);
            *(float4*)&sQPp[(0*2+bl)*Hdim + u*4] = *(const float4*)(Q  + (size_t)(b_base+bl)*Hdim + u*4);
            *(float4*)&sQPp[(1*2+bl)*Hdim + u*4] = *(const float4*)(PM + (size_t)(b_base+bl)*Hdim + u*4);
        }
    }
    __syncthreads();

    float acc[2][4][4];
    #pragma unroll
    for (int mf = 0; mf < 2; mf++)
        #pragma unroll
        for (int nb = 0; nb < 4; nb++)
            #pragma unroll
            for (int d = 0; d < 4; d++) acc[mf][nb][d] = 0.0f;

    auto G_fetchC = [&](int c, uint4* rr) {
        const int base0 = c * 32;
        const int r = tid >> 2, u = tid & 3;
        rr[0] = *(const uint4*)(g_C16 + (size_t)(m0 + r) * Hdim + base0 + u * 8);
    };
    auto G_storeA = [&](int c, uint32_t buf, const uint4* rr) {
        const int base0 = c * 32;
        const int r = tid >> 2, u = tid & 3;
        const __half* ch = (const __half*)&rr[0];
        float cf[8];
        #pragma unroll
        for (int j = 0; j < 8; j++) cf[j] = __half2float(ch[j]);
        const float* qv = &sQPp[(0*2+(r>>6))*Hdim + base0 + u*8];
        const float* pv = &sQPp[(1*2+(r>>6))*Hdim + base0 + u*8];
        #pragma unroll
        for (int part = 0; part < 4; part++) {
            const float* vv = (part & 1) ? pv : qv;
            uint32_t o[4];
            #pragma unroll
            for (int j = 0; j < 4; j++) {
                const float x0 = (part < 2) ? cf[2*j]   * vv[2*j]
                                            : fabsf(cf[2*j]   - vv[2*j]);
                const float x1 = (part < 2) ? cf[2*j+1] * vv[2*j+1]
                                            : fabsf(cf[2*j+1] - vv[2*j+1]);
                const __half2 hh = __floats2half2_rn(x0, x1);
                o[j] = *(const uint32_t*)&hh;
            }
            const uint4 v4 = make_uint4(o[0], o[1], o[2], o[3]);
            STS16(buf + part * GAp + r * LD + u * 16, v4);
        }
    };
    auto G_cpB = [&](int c, uint32_t buf) {
        const int base0 = c * 32;
        #pragma unroll
        for (int i = 0; i < 4; i++) {
            const int q = tid + i * 512;
            const int part = q >> 9, rem = q & 511;
            const int r = rem >> 2, u = rem & 3;
            CP16(buf + GA4 + part * GAp + r * LD + u * 16,
                 g_fc1w16 + (size_t)r * H4 + part * 512 + base0 + u * 8);
        }
    };

    uint4 rr[1];
    G_fetchC(0, rr);
    G_cpB(0, sb);
    CP_COMMIT();
    G_storeA(0, sb, rr);
    CP_WAIT0();
    __syncthreads();

    const uint32_t a_lane = (lane & 15) * LD + (lane >> 4) * 16;
    const uint32_t b_lane = ((lane >> 4) * 8 + (lane & 7)) * LD + ((lane >> 3) & 1) * 16;

    for (int c = 0; c < 16; c++) {
        const uint32_t cur = sb + (c & 1) * GST3;
        const uint32_t nxt = sb + ((c + 1) & 1) * GST3;
        if (c < 15) {
            G_fetchC(c + 1, rr);
            G_cpB(c + 1, nxt);
        }
        CP_COMMIT();
        #pragma unroll
        for (int part = 0; part < 4; part++) {
            #pragma unroll
            for (int kk = 0; kk < 2; kk++) {
                uint32_t a[2][4];
                #pragma unroll
                for (int mf = 0; mf < 2; mf++)
                    LDSM4(a[mf][0], a[mf][1], a[mf][2], a[mf][3],
                          cur + part * GAp + (wm * 32 + mf * 16) * LD + kk * 32 + a_lane);
                #pragma unroll
                for (int nbp = 0; nbp < 2; nbp++) {
                    uint32_t b0, b1, b2, b3;
                    LDSM4(b0, b1, b2, b3,
                          cur + GA4 + part * GAp + (wn * 32 + nbp * 16) * LD + kk * 32 + b_lane);
                    #pragma unroll
                    for (int mf = 0; mf < 2; mf++) {
                        mma16816(acc[mf][nbp*2],   a[mf][0], a[mf][1], a[mf][2], a[mf][3], b0, b1);
                        mma16816(acc[mf][nbp*2+1], a[mf][0], a[mf][1], a[mf][2], a[mf][3], b2, b3);
                    }
                }
            }
        }
        if (c < 15) G_storeA(c + 1, nxt, rr);
        CP_WAIT0();
        __syncthreads();
    }

    #pragma unroll
    for (int mf = 0; mf < 2; mf++) {
        #pragma unroll
        for (int half = 0; half < 2; half++) {
            float partial = 0.0f;
            #pragma unroll
            for (int nb = 0; nb < 4; nb++) {
                #pragma unroll
                for (int cc = 0; cc < 2; cc++) {
                    const int n = wn * 32 + nb * 8 + (lane & 3) * 2 + cc;
                    if (n < SHdim)
                        partial += fc2w[n] * tanhf_(acc[mf][nb][half*2+cc] + fc1b[n]);
                }
            }
            partial += __shfl_xor_sync(0xffffffffu, partial, 1);
            partial += __shfl_xor_sync(0xffffffffu, partial, 2);
            if ((lane & 3) == 0)
                redp[wn * 128 + wm * 32 + mf * 16 + half * 8 + (lane >> 2)] = partial;
        }
    }
    __syncthreads();
    if (tid < 128) {
        const int m = m0 + tid;
        g_G[(m & 63) * Bdim + (m >> 6)] =
            sigmoidf_(redp[0*128+tid] + redp[1*128+tid] + redp[2*128+tid] + redp[3*128+tid] + fc2b[0]);
    }
}

__device__ __forceinline__ void xg_ld(uint32_t buf, int tid, int m0, int n0, int c){
    const int k0 = c * 64;
    #pragma unroll
    for (int i = 0; i < 2; i++) {
        const int q = tid + i * 512;
        const int r = q >> 3, u = q & 7;
        CP16(buf + r * LD64 + u * 16, g_C16 + (size_t)(m0 + r) * Hdim + k0 + u * 8);
    }
    #pragma unroll
    for (int i = 0; i < 4; i++) {
        const int q = tid + i * 512;
        const int r = q >> 3, u = q & 7;
        CP16(buf + XA2 + r * LD64 + u * 16, g_Wih16 + (size_t)(n0 + r) * Hdim + k0 + u * 8);
    }
}

__device__ void xg_body(char* smx, const float* __restrict__ bih, int idx)
{
    const uint32_t sb = smem_u32(smx);
    const int tid = threadIdx.x, lane = tid & 31, wid = tid >> 5;
    const int wm = wid >> 3, wn = wid & 7;
    // n-fastest: consecutive CTAs share the same m-tile (A reuse in L2)
    const int m0 = (idx / 6) * 128, n0 = (idx % 6) * 256;

    float acc[4][4][4];
    #pragma unroll
    for (int a = 0; a < 4; a++)
        #pragma unroll
        for (int b = 0; b < 4; b++)
            #pragma unroll
            for (int d = 0; d < 4; d++) acc[a][b][d] = 0.0f;

    xg_ld(sb, tid, m0, n0, 0); CP_COMMIT();
    xg_ld(sb + XST, tid, m0, n0, 1); CP_COMMIT();
    xg_ld(sb + 2*XST, tid, m0, n0, 2); CP_COMMIT();

    const uint32_t a_lrow = (lane & 15) * LD64 + (lane >> 4) * 16;
    const uint32_t b_lrow = ((lane >> 4) * 8 + (lane & 7)) * LD64 + ((lane >> 3) & 1) * 16;

    for (int c = 0; c < 8; c++) {
        CP_WAIT2();
        __syncthreads();
        if (c + 3 < 8) xg_ld(sb + ((c + 3) & 3) * XST, tid, m0, n0, c + 3);
        CP_COMMIT();
        const uint32_t cur = sb + (c & 3) * XST;
        #pragma unroll
        for (int kk = 0; kk < 4; kk++) {
            uint32_t a[4][4];
            #pragma unroll
            for (int mf = 0; mf < 4; mf++)
                LDSM4(a[mf][0], a[mf][1], a[mf][2], a[mf][3],
                      cur + (wm * 64 + mf * 16) * LD64 + kk * 32 + a_lrow);
            #pragma unroll
            for (int nfp = 0; nfp < 2; nfp++) {
                uint32_t b0, b1, b2, b3;
                LDSM4(b0, b1, b2, b3,
                      cur + XA2 + (wn * 32 + nfp * 16) * LD64 + kk * 32 + b_lrow);
                #pragma unroll
                for (int mf = 0; mf < 4; mf++) {
                    mma16816(acc[mf][nfp*2],   a[mf][0], a[mf][1], a[mf][2], a[mf][3], b0, b1);
                    mma16816(acc[mf][nfp*2+1], a[mf][0], a[mf][1], a[mf][2], a[mf][3], b2, b3);
                }
            }
        }
    }

    #pragma unroll
    for (int mf = 0; mf < 4; mf++) {
        #pragma unroll
        for (int half = 0; half < 2; half++) {
            const int m = m0 + wm * 64 + mf * 16 + (lane >> 2) + half * 8;
            const size_t ob = ((size_t)(m & 63) * Bdim + (m >> 6)) * H3;
            #pragma unroll
            for (int nf = 0; nf < 4; nf++) {
                const int jj = n0 + wn * 32 + nf * 8 + (lane & 3) * 2;
                const float ox = acc[mf][nf][half*2+0] + bih[jj];
                const float oy = acc[mf][nf][half*2+1] + bih[jj+1];
                *(__half2*)(g_xg16 + ob + jj) = __floats2half2_rn(ox, oy);
            }
        }
    }
}

__global__ __launch_bounds__(512, 1) void Gxg_mma(
    const float* __restrict__ Q, const float* __restrict__ PM,
    const float* __restrict__ fc1b, const float* __restrict__ fc2w,
    const float* __restrict__ fc2b, const float* __restrict__ bih)
{
    extern __shared__ __align__(16) char smx[];
    if (blockIdx.x < 512) {
        G_body(smx, Q, PM, fc1b, fc2w, fc2b);
    } else {
        xg_body(smx, bih, blockIdx.x - 512);
    }
}

// ---------------------------------------------------------------------------
// Persistent GRU: Whh resident; register-carried h; per-b-tile monotonic
// counter barrier (tid0 poll).
// ---------------------------------------------------------------------------
#define WB_SZ (192*WLD)            // 199680
#define GAST (64*LD64)             // 9216/stage, 3 stages
#define GRU_SMEM (WB_SZ + 3*GAST)  // 227328

__device__ __forceinline__ void gru_ldA(uint32_t dst, int tid, int b0, int c,
                                        const __half* __restrict__ h16){
    const int k0 = c * 64;
    #pragma unroll
    for (int i = 0; i < 2; i++) {
        const int q = tid + i * 256;
        const int r = q >> 3, u = q & 7;
        CP16(dst + r * LD64 + u * 16, h16 + (size_t)(b0 + r) * Hdim + k0 + u * 8);
    }
}

__global__ __launch_bounds__(256, 1) void gru_pers(
    const float* __restrict__ bhh, float* __restrict__ outp)
{
    extern __shared__ __align__(16) char smp[];
    const uint32_t sb = smem_u32(smp);
    const uint32_t WB = sb;
    const uint32_t AB = sb + WB_SZ;
    const int tid = threadIdx.x, lane = tid & 31, wid = tid >> 5;
    const int wm = wid >> 2, wn = wid & 3;
    const int bt = blockIdx.x;
    const int b0 = bt * 64, j0 = blockIdx.y * 64;
    unsigned* const cnt = &g_grp_cnt[bt * 32];

    for (int q = tid; q < 12288; q += 256) {
        const int r = q >> 6, u = q & 63;
        const int g = r >> 6, jj = r & 63;
        uint4 v = *(const uint4*)(g_Whh16 + (size_t)((g << 9) + j0 + jj) * Hdim + u * 8);
        STS16(WB + r * WLD + u * 16, v);
    }
    __syncthreads();

    const uint32_t a_lrow = (lane & 15) * LD64 + (lane >> 4) * 16;
    const uint32_t b_lrowW = ((lane >> 4) * 8 + (lane & 7)) * WLD + ((lane >> 3) & 1) * 16;

    const int jjb = j0 + wn * 16 + (lane & 3) * 2;
    const int brow[4] = {
        b0 + wm * 32 + (lane >> 2),
        b0 + wm * 32 + (lane >> 2) + 8,
        b0 + wm * 32 + 16 + (lane >> 2),
        b0 + wm * 32 + 16 + (lane >> 2) + 8
    };

    float2 bhh_r[3][2];
    #pragma unroll
    for (int g = 0; g < 3; g++)
        #pragma unroll
        for (int nfp = 0; nfp < 2; nfp++)
            bhh_r[g][nfp] = *(const float2*)(bhh + g * Hdim + jjb + nfp * 8);

    float hold[4][2][2];
    #pragma unroll
    for (int r4 = 0; r4 < 4; r4++)
        #pragma unroll
        for (int nfp = 0; nfp < 2; nfp++) { hold[r4][nfp][0] = 0.0f; hold[r4][nfp][1] = 0.0f; }

    for (int s = 0; s < Sdim; s++) {
        const int par = s & 1;
        const __half* __restrict__ h16 = g_h16[par];

        float acc[2][3][2][4];
        #pragma unroll
        for (int mf = 0; mf < 2; mf++)
            #pragma unroll
            for (int g = 0; g < 3; g++)
                #pragma unroll
                for (int nfp = 0; nfp < 2; nfp++)
                    #pragma unroll
                    for (int d = 0; d < 4; d++) acc[mf][g][nfp][d] = 0.0f;

        gru_ldA(AB, tid, b0, 0, h16); CP_COMMIT();
        gru_ldA(AB + GAST, tid, b0, 1, h16); CP_COMMIT();

        float gate[4];
        #pragma unroll
        for (int r4 = 0; r4 < 4; r4++) gate[r4] = g_G[s * Bdim + brow[r4]];
        __half2 xgp[4][3][2];
        #pragma unroll
        for (int r4 = 0; r4 < 4; r4++) {
            const __half* xrow = g_xg16 + ((size_t)s * Bdim + brow[r4]) * H3;
            #pragma unroll
            for (int g = 0; g < 3; g++)
                #pragma unroll
                for (int nfp = 0; nfp < 2; nfp++)
                    xgp[r4][g][nfp] = *(const __half2*)(xrow + g * Hdim + jjb + nfp * 8);
        }

        for (int c = 0; c < 8; c++) {
            CP_WAIT1();
            __syncthreads();
            if (c + 2 < 8) gru_ldA(AB + ((c + 2) % 3) * GAST, tid, b0, c + 2, h16);
            CP_COMMIT();
            const uint32_t cur = AB + (c % 3) * GAST;
            const uint32_t koff = c * 128;
            #pragma unroll
            for (int kk = 0; kk < 4; kk++) {
                uint32_t a[2][4];
                #pragma unroll
                for (int mf = 0; mf < 2; mf++)
                    LDSM4(a[mf][0], a[mf][1], a[mf][2], a[mf][3],
                          cur + (wm * 32 + mf * 16) * LD64 + a_lrow + kk * 32);
                #pragma unroll
                for (int g = 0; g < 3; g++) {
                    uint32_t b0r, b1r, b2r, b3r;
                    LDSM4(b0r, b1r, b2r, b3r,
                          WB + (g * 64 + wn * 16) * WLD + koff + kk * 32 + b_lrowW);
                    #pragma unroll
                    for (int mf = 0; mf < 2; mf++) {
                        mma16816(acc[mf][g][0], a[mf][0], a[mf][1], a[mf][2], a[mf][3], b0r, b1r);
                        mma16816(acc[mf][g][1], a[mf][0], a[mf][1], a[mf][2], a[mf][3], b2r, b3r);
                    }
                }
            }
        }

        const int last = (s == Sdim - 1);
        __half* __restrict__ h16N = g_h16[par ^ 1];

        #pragma unroll
        for (int mf = 0; mf < 2; mf++) {
            #pragma unroll
            for (int half = 0; half < 2; half++) {
                const int r4 = mf * 2 + half;
                const int bb = brow[r4];
                const float gt = gate[r4];
                #pragma unroll
                for (int nfp = 0; nfp < 2; nfp++) {
                    float hn2[2];
                    #pragma unroll
                    for (int cc = 0; cc < 2; cc++) {
                        const int ai = half * 2 + cc;
                        const float hr = acc[mf][0][nfp][ai] + (cc ? bhh_r[0][nfp].y : bhh_r[0][nfp].x);
                        const float hz = acc[mf][1][nfp][ai] + (cc ? bhh_r[1][nfp].y : bhh_r[1][nfp].x);
                        const float hnv = acc[mf][2][nfp][ai] + (cc ? bhh_r[2][nfp].y : bhh_r[2][nfp].x);
                        const float xr = cc ? __high2float(xgp[r4][0][nfp]) : __low2float(xgp[r4][0][nfp]);
                        const float xz = cc ? __high2float(xgp[r4][1][nfp]) : __low2float(xgp[r4][1][nfp]);
                        const float xn = cc ? __high2float(xgp[r4][2][nfp]) : __low2float(xgp[r4][2][nfp]);
                        const float r = sigmoidf_(xr + hr);
                        const float z = sigmoidf_(xz + hz);
                        const float n = tanhf_(xn + r * hnv);
                        const float ho = hold[r4][nfp][cc];
                        const float hnew = gt * ((1.0f - z) * n + z * ho) + (1.0f - gt) * ho;
                        hold[r4][nfp][cc] = hnew;
                        hn2[cc] = hnew;
                    }
                    if (last) {
                        *(float2*)(outp + (size_t)bb * Hdim + jjb + nfp * 8) = make_float2(hn2[0], hn2[1]);
                    } else {
                        *(__half2*)(h16N + (size_t)bb * Hdim + jjb + nfp * 8) = __floats2half2_rn(hn2[0], hn2[1]);
                    }
                }
            }
        }

        if (!last) {
            __syncthreads();
            if (tid == 0) {
                __threadfence();
                atomicAdd(cnt, 1u);                     // monotonic arrival
                const unsigned target = 8u * (unsigned)(s + 1);
                unsigned v;
                do {
                    asm volatile("ld.acquire.gpu.u32 %0, [%1];" : "=r"(v) : "l"(cnt));
                } while (v < target);
            }
            __syncthreads();
        }
    }
}

// ---------------------------------------------------------------------------
extern "C" void kernel_launch(void* const* d_in, const int* in_sizes, int n_in,
                              void* d_out, int out_size)
{
    const float* C    = (const float*)d_in[0];
    const float* Q    = (const float*)d_in[1];
    const float* PM   = (const float*)d_in[2];
    const float* fc1w = (const float*)d_in[3];
    const float* fc1b = (const float*)d_in[4];
    const float* fc2w = (const float*)d_in[5];
    const float* fc2b = (const float*)d_in[6];
    const float* Wih  = (const float*)d_in[7];
    const float* Whh  = (const float*)d_in[8];
    const float* bih  = (const float*)d_in[9];
    const float* bhh  = (const float*)d_in[10];
    float* out = (float*)d_out;

    static int configured = 0;
    if (!configured) {
        cudaFuncSetAttribute(Gxg_mma,  cudaFuncAttributeMaxDynamicSharedMemorySize, MERGED_SMEM);
        cudaFuncSetAttribute(gru_pers, cudaFuncAttributeMaxDynamicSharedMemorySize, GRU_SMEM);
        configured = 1;
    }

    prologue_kernel<<<(PRO_TOTAL + 255) / 256, 256>>>(C, Wih, Whh, fc1w);
    Gxg_mma<<<512 + 3072, 512, MERGED_SMEM>>>(Q, PM, fc1b, fc2w, fc2b, bih);
    gru_pers<<<dim3(Bdim/64, Hdim/64), 256, GRU_SMEM>>>(bhh, out);
}